// round 9
// baseline (speedup 1.0000x reference)
#include <cuda_runtime.h>
#include <cuda_bf16.h>
#include <math.h>

#define Bb 8
#define Tt 2048
#define Cc 1024
#define Hh 16
#define Nn 64
#define Mrows 16384
#define BTC 16777216

typedef __nv_bfloat16 bf16;
typedef unsigned long long ull;

// ---------------- fp32 scratch ----------------
__device__ float g_R[BTC], g_K[BTC], g_V[BTC], g_A[BTC], g_G[BTC];
__device__ float g_WD[BTC], g_KK[BTC], g_Y[BTC];

// ---------------- bf16 hi/lo planes ----------------
__device__ __align__(256) bf16 g_XH[6l*BTC];
__device__ __align__(256) bf16 g_XL[6l*BTC];
__device__ __align__(256) bf16 g_WH[5242880];    // packed weights [K,N] padded
__device__ __align__(256) bf16 g_WL[5242880];
__device__ __align__(256) bf16 g_HH[4l*Mrows*128];
__device__ __align__(256) bf16 g_HL[4l*Mrows*128];
__device__ __align__(256) bf16 g_YGH[BTC];
__device__ __align__(256) bf16 g_YGL[BTC];

#define W_R  0
#define W_K  1048576
#define W_V  2097152
#define W_O  3145728
#define W_L(i) (4194304 + (i)*131072)

__device__ __forceinline__ float sigm(float x){ return 1.0f/(1.0f+expf(-x)); }
__device__ __forceinline__ void split2(float v, bf16& h, bf16& l){
    h = __float2bfloat16(v); l = __float2bfloat16(v - __bfloat162float(h));
}

__device__ __forceinline__ void cpa16(unsigned dst, const void* src) {
    asm volatile("cp.async.cg.shared.global [%0], [%1], 16;" :: "r"(dst), "l"(src));
}
__device__ __forceinline__ void cpcommit(){ asm volatile("cp.async.commit_group;"); }
__device__ __forceinline__ void cpwait2(){ asm volatile("cp.async.wait_group 2;"); }

__device__ __forceinline__ void ldmat4(unsigned& r0, unsigned& r1, unsigned& r2, unsigned& r3,
                                       unsigned addr) {
    asm volatile("ldmatrix.sync.aligned.m8n8.x4.shared.b16 {%0,%1,%2,%3}, [%4];"
                 : "=r"(r0), "=r"(r1), "=r"(r2), "=r"(r3) : "r"(addr));
}
__device__ __forceinline__ void ldmat4t(unsigned& r0, unsigned& r1, unsigned& r2, unsigned& r3,
                                        unsigned addr) {
    asm volatile("ldmatrix.sync.aligned.m8n8.x4.trans.shared.b16 {%0,%1,%2,%3}, [%4];"
                 : "=r"(r0), "=r"(r1), "=r"(r2), "=r"(r3) : "r"(addr));
}
__device__ __forceinline__ void mma16816(float* c, const unsigned* a, unsigned b0, unsigned b1) {
    asm volatile("mma.sync.aligned.m16n8k16.row.col.f32.bf16.bf16.f32 "
                 "{%0,%1,%2,%3}, {%4,%5,%6,%7}, {%8,%9}, {%0,%1,%2,%3};"
                 : "+f"(c[0]), "+f"(c[1]), "+f"(c[2]), "+f"(c[3])
                 : "r"(a[0]), "r"(a[1]), "r"(a[2]), "r"(a[3]), "r"(b0), "r"(b1));
}

// packed f32x2
__device__ __forceinline__ ull fma2(ull a, ull b, ull c){
    ull d; asm("fma.rn.f32x2 %0, %1, %2, %3;" : "=l"(d) : "l"(a), "l"(b), "l"(c)); return d;
}
__device__ __forceinline__ ull mul2(ull a, ull b){
    ull d; asm("mul.rn.f32x2 %0, %1, %2;" : "=l"(d) : "l"(a), "l"(b)); return d;
}
__device__ __forceinline__ ull pack2(float x){
    ull d; asm("mov.b64 %0, {%1, %1};" : "=l"(d) : "f"(x)); return d;
}
__device__ __forceinline__ float sum2(ull v){
    float lo, hi; asm("mov.b64 {%0, %1}, %2;" : "=f"(lo), "=f"(hi) : "l"(v)); return lo + hi;
}

// ============================================================================
// prep: mix x with 6 maa vectors, split to bf16 hi/lo planes.
// ============================================================================
__global__ void __launch_bounds__(256) prep_kernel(
    const float* __restrict__ x,
    const float* __restrict__ m0, const float* __restrict__ m1,
    const float* __restrict__ m2, const float* __restrict__ m3,
    const float* __restrict__ m4, const float* __restrict__ m5)
{
    long e = ((long)blockIdx.x*256 + threadIdx.x)*4;
    int r = (int)(e >> 10), c = (int)(e & 1023);
    float4 cur = *(const float4*)(x + e);
    float4 prv = make_float4(0.f,0.f,0.f,0.f);
    if ((r & (Tt-1)) != 0) prv = *(const float4*)(x + e - Cc);
    float d0 = prv.x-cur.x, d1 = prv.y-cur.y, d2 = prv.z-cur.z, d3 = prv.w-cur.w;
    const float* maas[6] = {m0,m1,m2,m3,m4,m5};
    #pragma unroll
    for (int v = 0; v < 6; v++) {
        float4 mv = *(const float4*)(maas[v] + c);
        float a0 = cur.x + d0*mv.x, a1 = cur.y + d1*mv.y;
        float a2 = cur.z + d2*mv.z, a3 = cur.w + d3*mv.w;
        bf16 h0,l0,h1,l1,h2,l2,h3,l3;
        split2(a0,h0,l0); split2(a1,h1,l1); split2(a2,h2,l2); split2(a3,h3,l3);
        long o = (long)v*BTC + e;
        *(__nv_bfloat162*)&g_XH[o]   = __nv_bfloat162(h0,h1);
        *(__nv_bfloat162*)&g_XH[o+2] = __nv_bfloat162(h2,h3);
        *(__nv_bfloat162*)&g_XL[o]   = __nv_bfloat162(l0,l1);
        *(__nv_bfloat162*)&g_XL[o+2] = __nv_bfloat162(l2,l3);
    }
}

// ============================================================================
// wsplit_all: split ALL weights in one launch.
// Layout: 4 big [1024x1024] at 0..4M, then 4 stage-1 [1024 x N->128] and
// 4 stage-2 [K->128 x 1024], 128K elements each.
// ============================================================================
struct WPtrs { const float* w[12]; };

__global__ void __launch_bounds__(256) wsplit_all(WPtrs p)
{
    long g = (long)blockIdx.x*256 + threadIdx.x;   // < 5242880
    float v;
    if (g < 4194304) {
        int which = (int)(g >> 20);
        int off = (int)(g & 1048575);
        v = p.w[which][off];
    } else {
        long h = g - 4194304;
        int i = (int)(h >> 17);
        int off = (int)(h & 131071);
        if (i < 4) {              // stage-1: [1024, Nreal] -> padded [1024,128]
            int r = off >> 7, c = off & 127;
            int Nreal = (i==2) ? 128 : ((i==3) ? 32 : 64);
            v = (c < Nreal) ? p.w[4+i][(long)r*Nreal + c] : 0.f;
        } else {                  // stage-2: [Kreal, 1024] -> padded [128,1024]
            int j = i - 4;
            int r = off >> 10, c = off & 1023;
            int Kreal = (j==2) ? 128 : ((j==3) ? 32 : 64);
            v = (r < Kreal) ? p.w[8+j][(long)r*1024 + c] : 0.f;
        }
    }
    bf16 hh, ll; split2(v, hh, ll);
    g_WH[g] = hh; g_WL[g] = ll;
}

// ============================================================================
// mma.sync GEMM: C[M,N] = A[M,K] @ B[K,N], bf16 hi/lo 3-pass, fp32 accum.
// CTA tile 128x128, BK=32, 4-stage cp.async, ONE barrier per k-iter.
// 8 warps (2Mx4N), warp tile 64x32. blockIdx.z selects one of 3 GArg sets.
// epi: 0 none; 1 exp(-sigm(bias+v)*e^-.5); 2 sigm(bias+v);
//      3 vmix C=C+(vaux-C)*sigm(bias+v); 4 tanh; 5 sigm
// outmode: 0 fp32 -> Cf; 1 bf16 hi/lo planes -> ChH/ChL
// ============================================================================
#define AST 40
#define BST 136
#define A_PL 10240           // bytes per A plane (128*40*2)
#define B_OFF 20480
#define B_PL 8704            // bytes per B plane (32*136*2)
#define STG 37888
#define SMEM_REQ (4*STG)     // 151552 B

struct GArg {
    const bf16 *Ah, *Al, *Bh, *Bl;
    float* Cf; bf16 *ChH, *ChL;
    const float *bias, *vaux;
    int epi, outmode;
};

__global__ void __launch_bounds__(256) gemm_bf16(GArg g0, GArg g1, GArg g2, int N, int K)
{
    extern __shared__ __align__(16) char smem[];
    const unsigned smemU = (unsigned)__cvta_generic_to_shared(smem);

    const GArg ga = (blockIdx.z == 0) ? g0 : ((blockIdx.z == 1) ? g1 : g2);
    const bf16* __restrict__ Ah = ga.Ah;  const bf16* __restrict__ Al = ga.Al;
    const bf16* __restrict__ Bh = ga.Bh;  const bf16* __restrict__ Bl = ga.Bl;

    const int tid  = threadIdx.x;
    const int bm   = blockIdx.y, bn = blockIdx.x;
    const int warp = tid >> 5, lane = tid & 31;
    const int wm   = warp & 1,  wn  = warp >> 1;

    float acc[4][4][4];
    #pragma unroll
    for (int i = 0; i < 4; i++)
        #pragma unroll
        for (int j = 0; j < 4; j++)
            #pragma unroll
            for (int e = 0; e < 4; e++) acc[i][j][e] = 0.f;

    // fragment addressing (validated R3/R4 scheme)
    const int aRow  = wm*64 + (lane & 7) + ((lane >> 3) & 1)*8;
    const int aCsel = (lane >> 4)*8;
    const unsigned aBaseOff = (unsigned)(aRow*AST + aCsel)*2;
    const int bKrow = ((lane >> 3) & 1)*8 + (lane & 7);
    const int bNcol = wn*32 + (lane >> 4)*8;
    const unsigned bBaseOff = (unsigned)(bKrow*BST + bNcol)*2;

    const int NIT = K >> 5;

    // ---- stage loader: 8 cp.async per thread ----
    const int ar = tid >> 2, ac = (tid & 3)*8;
    const int br = tid >> 4, bc = (tid & 15)*8;
    auto issue = [&](int s, int k0) {
        unsigned sb = smemU + s*STG;
        #pragma unroll
        for (int u = 0; u < 2; u++) {
            int r = ar + u*64;
            unsigned so = (unsigned)(r*AST + ac)*2;
            cpa16(sb + so,        Ah + (long)(bm*128 + r)*K + k0 + ac);
            cpa16(sb + A_PL + so, Al + (long)(bm*128 + r)*K + k0 + ac);
            int r2 = br + u*16;
            unsigned so2 = (unsigned)(r2*BST + bc)*2;
            cpa16(sb + B_OFF + so2,        Bh + (long)(k0 + r2)*N + bn*128 + bc);
            cpa16(sb + B_OFF + B_PL + so2, Bl + (long)(k0 + r2)*N + bn*128 + bc);
        }
        cpcommit();
    };

    issue(0, 0);
    issue(1, 32);
    issue(2, 64);               // K >= 96 always (K in {128,1024})

    for (int s = 0; s < NIT; s++) {
        cpwait2();              // stage s complete (one group per iter, incl. empties)
        __syncthreads();        // publish to all warps; also fences stage (s-1)%4 reads
        if (s + 3 < NIT) issue((s + 3) & 3, (s + 3)*32); else cpcommit();

        unsigned sb = smemU + (s & 3)*STG;
        unsigned aH = sb + aBaseOff;
        unsigned aL = aH + A_PL;
        unsigned bH = sb + B_OFF + bBaseOff;
        unsigned bL = bH + B_PL;

        #pragma unroll
        for (int ks = 0; ks < 2; ks++) {
            unsigned ah[4][4], al[4][4], bh[2][4], bl[2][4];
            #pragma unroll
            for (int i = 0; i < 4; i++) {
                unsigned off = (unsigned)(i*16*AST + ks*16)*2;
                ldmat4(ah[i][0], ah[i][1], ah[i][2], ah[i][3], aH + off);
                ldmat4(al[i][0], al[i][1], al[i][2], al[i][3], aL + off);
            }
            #pragma unroll
            for (int jj = 0; jj < 2; jj++) {
                unsigned off = (unsigned)(ks*16*BST + jj*16)*2;
                ldmat4t(bh[jj][0], bh[jj][1], bh[jj][2], bh[jj][3], bH + off);
                ldmat4t(bl[jj][0], bl[jj][1], bl[jj][2], bl[jj][3], bL + off);
            }
            #pragma unroll
            for (int i = 0; i < 4; i++)
                #pragma unroll
                for (int j = 0; j < 4; j++) {
                    int jj = j >> 1, sel = (j & 1)*2;
                    mma16816(acc[i][j], ah[i], bh[jj][sel], bh[jj][sel+1]);
                    mma16816(acc[i][j], ah[i], bl[jj][sel], bl[jj][sel+1]);
                    mma16816(acc[i][j], al[i], bh[jj][sel], bh[jj][sel+1]);
                }
        }
    }

    // ---- epilogue ----
    const int g = lane >> 2, q = lane & 3;
    #pragma unroll
    for (int i = 0; i < 4; i++) {
        int r0 = bm*128 + wm*64 + i*16 + g;
        #pragma unroll
        for (int j = 0; j < 4; j++) {
            int col = bn*128 + wn*32 + j*8 + q*2;
            #pragma unroll
            for (int h = 0; h < 2; h++) {
                int row = r0 + h*8;
                long idx = (long)row*N + col;
                float v0 = acc[i][j][h*2], v1 = acc[i][j][h*2+1];
                if (ga.epi == 1) {
                    v0 = expf(-sigm(ga.bias[col]  +v0)*0.60653065971263342f);
                    v1 = expf(-sigm(ga.bias[col+1]+v1)*0.60653065971263342f);
                } else if (ga.epi == 2) {
                    v0 = sigm(ga.bias[col]+v0); v1 = sigm(ga.bias[col+1]+v1);
                } else if (ga.epi == 3) {
                    float s0 = sigm(ga.bias[col]+v0), s1 = sigm(ga.bias[col+1]+v1);
                    float c0 = ga.Cf[idx], c1 = ga.Cf[idx+1];
                    v0 = c0 + (ga.vaux[idx]  -c0)*s0;
                    v1 = c1 + (ga.vaux[idx+1]-c1)*s1;
                } else if (ga.epi == 4) {
                    v0 = tanhf(v0); v1 = tanhf(v1);
                } else if (ga.epi == 5) {
                    v0 = sigm(v0); v1 = sigm(v1);
                }
                if (ga.outmode == 0) {
                    *(float2*)&ga.Cf[idx] = make_float2(v0, v1);
                } else {
                    bf16 h0,l0,h1,l1;
                    split2(v0,h0,l0); split2(v1,h1,l1);
                    *(__nv_bfloat162*)&ga.ChH[idx] = __nv_bfloat162(h0,h1);
                    *(__nv_bfloat162*)&ga.ChL[idx] = __nv_bfloat162(l0,l1);
                }
            }
        }
    }
}

// ============================================================================
// kk normalize + k update.
// ============================================================================
__global__ void kk_kernel(const float* __restrict__ Kin, const float* __restrict__ Aa,
                          const float* __restrict__ mkk, const float* __restrict__ ma,
                          float* __restrict__ KKo, float* __restrict__ K2o)
{
    int gw   = (blockIdx.x*blockDim.x + threadIdx.x) >> 5;
    int lane = threadIdx.x & 31;
    long off = (long)gw*64 + lane*2;
    int  c   = ((gw & (Hh-1))*64) + lane*2;
    float2 kv = *(const float2*)(Kin + off);
    float2 mk = *(const float2*)(mkk + c);
    float kk0 = kv.x*mk.x, kk1 = kv.y*mk.y;
    float ss = kk0*kk0 + kk1*kk1;
    #pragma unroll
    for (int s = 16; s > 0; s >>= 1) ss += __shfl_xor_sync(0xffffffffu, ss, s);
    float inv = 1.0f / fmaxf(sqrtf(ss), 1e-12f);
    *(float2*)(KKo + off) = make_float2(kk0*inv, kk1*inv);
    float2 av  = *(const float2*)(Aa + off);
    float2 mav = *(const float2*)(ma + c);
    *(float2*)(K2o + off) = make_float2(kv.x*(1.f+(av.x-1.f)*mav.x),
                                        kv.y*(1.f+(av.y-1.f)*mav.y));
}

// ============================================================================
// RWKV7 scan: 128 threads per (b,h); thread owns half a state row; f32x2 FMA.
// ============================================================================
__global__ void __launch_bounds__(128) scan_kernel(
    const float* __restrict__ R,  const float* __restrict__ W,
    const float* __restrict__ K2, const float* __restrict__ V,
    const float* __restrict__ KK, const float* __restrict__ Aa,
    float* __restrict__ Y)
{
    const int bh = blockIdx.x;
    const int b  = bh >> 4, hh = bh & 15;
    const int tid  = threadIdx.x;
    const int i    = tid >> 1;
    const int half = tid & 1;
    const int cb   = half*32;
    const long rowbase = (long)b*Tt*Cc + hh*Nn;

    __shared__ __align__(16) float sm[2][6][Nn];

    ull S2[16];
    #pragma unroll
    for (int j = 0; j < 16; j++) S2[j] = 0ull;

    auto loadstage = [&](int q, int t) {
        long idx = rowbase + (long)t*Cc;
        if (tid < 64) {
            sm[q][0][tid] = R[idx+tid];
            sm[q][1][tid] = W[idx+tid];
            sm[q][2][tid] = K2[idx+tid];
        } else {
            int j = tid - 64;
            sm[q][3][j] = V[idx+j];
            float kk = KK[idx+j], a = Aa[idx+j];
            sm[q][4][j] = kk; sm[q][5][j] = kk*a;
        }
    };

    loadstage(0, 0);
    __syncthreads();

    int p = 0;
    for (int t = 0; t < Tt; t++) {
        if (t + 1 < Tt) loadstage(p^1, t+1);
        const ull* r2  = (const ull*)&sm[p][0][cb];
        const ull* w2  = (const ull*)&sm[p][1][cb];
        const ull* k2  = (const ull*)&sm[p][2][cb];
        const ull* kk2 = (const ull*)&sm[p][4][cb];
        const ull* b2  = (const ull*)&sm[p][5][cb];
        const float vi = sm[p][3][i];

        ull sa_a = 0ull, sa_b = 0ull;
        #pragma unroll
        for (int j = 0; j < 16; j += 2) {
            sa_a = fma2(S2[j],   kk2[j],   sa_a);
            sa_b = fma2(S2[j+1], kk2[j+1], sa_b);
        }
        float sa_p = sum2(sa_a) + sum2(sa_b);
        float sa = -(sa_p + __shfl_xor_sync(0xffffffffu, sa_p, 1));

        ull sa2 = pack2(sa), vi2 = pack2(vi);
        ull o_a = 0ull, o_b = 0ull;
        #pragma unroll
        for (int j = 0; j < 16; j += 2) {
            ull t0 = fma2(sa2, b2[j],   mul2(vi2, k2[j]));
            ull t1 = fma2(sa2, b2[j+1], mul2(vi2, k2[j+1]));
            S2[j]   = fma2(S2[j],   w2[j],   t0);
            S2[j+1] = fma2(S2[j+1], w2[j+1], t1);
            o_a = fma2(S2[j],   r2[j],   o_a);
            o_b = fma2(S2[j+1], r2[j+1], o_b);
        }
        float o_p = sum2(o_a) + sum2(o_b);
        float o = o_p + __shfl_xor_sync(0xffffffffu, o_p, 1);
        if (half == 0) Y[rowbase + (long)t*Cc + i] = o;
        __syncthreads();
        p ^= 1;
    }
}

// ============================================================================
// GroupNorm + rkv bonus + gate -> bf16 hi/lo planes.
// ============================================================================
__global__ void post_kernel(const float* __restrict__ Y,  const float* __restrict__ R,
                            const float* __restrict__ K2, const float* __restrict__ V,
                            const float* __restrict__ G,  const float* __restrict__ faaaa,
                            const float* __restrict__ lnw,const float* __restrict__ lnb)
{
    int gw   = (blockIdx.x*blockDim.x + threadIdx.x) >> 5;
    int lane = threadIdx.x & 31;
    long off = (long)gw*64 + lane*2;
    int  c   = ((gw & 15)*64) + lane*2;
    float2 y  = *(const float2*)(Y + off);
    float2 r  = *(const float2*)(R + off);
    float2 k  = *(const float2*)(K2 + off);
    float2 fa = *(const float2*)(faaaa + c);
    float s1 = y.x + y.y;
    float s2 = y.x*y.x + y.y*y.y;
    float rk = r.x*k.x*fa.x + r.y*k.y*fa.y;
    #pragma unroll
    for (int s = 16; s > 0; s >>= 1) {
        s1 += __shfl_xor_sync(0xffffffffu, s1, s);
        s2 += __shfl_xor_sync(0xffffffffu, s2, s);
        rk += __shfl_xor_sync(0xffffffffu, rk, s);
    }
    float mu  = s1 * (1.0f/64.0f);
    float var = s2 * (1.0f/64.0f) - mu*mu;
    float rs  = rsqrtf(var + 6.4e-4f);
    float2 w2 = *(const float2*)(lnw + c);
    float2 b2 = *(const float2*)(lnb + c);
    float2 v  = *(const float2*)(V + off);
    float2 g  = *(const float2*)(G + off);
    float o0 = ((y.x-mu)*rs*w2.x + b2.x + rk*v.x) * g.x;
    float o1 = ((y.y-mu)*rs*w2.y + b2.y + rk*v.y) * g.y;
    bf16 h0,l0,h1,l1;
    split2(o0,h0,l0); split2(o1,h1,l1);
    *(__nv_bfloat162*)&g_YGH[off] = __nv_bfloat162(h0,h1);
    *(__nv_bfloat162*)&g_YGL[off] = __nv_bfloat162(l0,l1);
}

__global__ void copy_kernel(const float* __restrict__ src, float* __restrict__ dst, int n4)
{
    int idx = blockIdx.x*blockDim.x + threadIdx.x;
    if (idx < n4) ((float4*)dst)[idx] = ((const float4*)src)[idx];
}

// ============================================================================
extern "C" void kernel_launch(void* const* d_in, const int* in_sizes, int n_in,
                              void* d_out, int out_size)
{
    const float* x        = (const float*)d_in[0];
    const float* v0       = (const float*)d_in[1];
    const float* maa_r    = (const float*)d_in[2];
    const float* maa_w    = (const float*)d_in[3];
    const float* maa_k    = (const float*)d_in[4];
    const float* maa_v    = (const float*)d_in[5];
    const float* maa_a    = (const float*)d_in[6];
    const float* maa_g    = (const float*)d_in[7];
    const float* tdecay   = (const float*)d_in[8];
    const float* faaaa    = (const float*)d_in[9];
    const float* taaaaa   = (const float*)d_in[10];
    const float* decay_w1 = (const float*)d_in[11];
    const float* decay_w2 = (const float*)d_in[12];
    const float* aaa_w1   = (const float*)d_in[13];
    const float* aaa_w2   = (const float*)d_in[14];
    const float* gate_w1  = (const float*)d_in[15];
    const float* gate_w2  = (const float*)d_in[16];
    const float* mv_w1    = (const float*)d_in[17];
    const float* mv_w2    = (const float*)d_in[18];
    const float* misc_v   = (const float*)d_in[19];
    const float* misc_kkk = (const float*)d_in[20];
    const float* misc_a   = (const float*)d_in[21];
    const float* W_r      = (const float*)d_in[22];
    const float* W_k      = (const float*)d_in[23];
    const float* W_v      = (const float*)d_in[24];
    const float* W_out    = (const float*)d_in[25];
    const float* ln_w     = (const float*)d_in[26];
    const float* ln_b     = (const float*)d_in[27];

    static float *pR=nullptr,*pK,*pV,*pA,*pG,*pWD,*pKK,*pY;
    static bf16 *pXH,*pXL,*pWH,*pWL,*pHH,*pHL,*pYGH,*pYGL;
    if (!pR) {
        cudaGetSymbolAddress((void**)&pR,  g_R);
        cudaGetSymbolAddress((void**)&pK,  g_K);
        cudaGetSymbolAddress((void**)&pV,  g_V);
        cudaGetSymbolAddress((void**)&pA,  g_A);
        cudaGetSymbolAddress((void**)&pG,  g_G);
        cudaGetSymbolAddress((void**)&pWD, g_WD);
        cudaGetSymbolAddress((void**)&pKK, g_KK);
        cudaGetSymbolAddress((void**)&pY,  g_Y);
        cudaGetSymbolAddress((void**)&pXH, g_XH);
        cudaGetSymbolAddress((void**)&pXL, g_XL);
        cudaGetSymbolAddress((void**)&pWH, g_WH);
        cudaGetSymbolAddress((void**)&pWL, g_WL);
        cudaGetSymbolAddress((void**)&pHH, g_HH);
        cudaGetSymbolAddress((void**)&pHL, g_HL);
        cudaGetSymbolAddress((void**)&pYGH, g_YGH);
        cudaGetSymbolAddress((void**)&pYGL, g_YGL);
        cudaFuncSetAttribute(gemm_bf16, cudaFuncAttributeMaxDynamicSharedMemorySize, SMEM_REQ);
    }

    const long MH = (long)Mrows*128;
    auto GA = [&](const bf16* Ah, const bf16* Al, long wOff,
                  float* Cf, bf16* ChH, bf16* ChL,
                  const float* bias, const float* vaux, int epi, int outmode) {
        GArg a;
        a.Ah = Ah; a.Al = Al; a.Bh = pWH + wOff; a.Bl = pWL + wOff;
        a.Cf = Cf; a.ChH = ChH; a.ChL = ChL;
        a.bias = bias; a.vaux = vaux; a.epi = epi; a.outmode = outmode;
        return a;
    };

    // launch 0: prep
    prep_kernel<<<BTC/1024, 256>>>(x, maa_r, maa_w, maa_k, maa_v, maa_a, maa_g);

    // launch 1: all weight splits fused
    WPtrs wp;
    wp.w[0]=W_r; wp.w[1]=W_k; wp.w[2]=W_v; wp.w[3]=W_out;
    wp.w[4]=decay_w1; wp.w[5]=aaa_w1; wp.w[6]=gate_w1; wp.w[7]=mv_w1;
    wp.w[8]=decay_w2; wp.w[9]=aaa_w2; wp.w[10]=gate_w2; wp.w[11]=mv_w2;
    wsplit_all<<<20480, 256>>>(wp);

    dim3 gBig(8, 128, 1), gRKV(8, 128, 3), gNar(1, 128, 1);

    // launches 2-4: three LoRA stage-1 GEMMs (N=128, K=1024)
    GArg aW  = GA(pXH+1l*BTC, pXL+1l*BTC, W_L(0), nullptr, pHH+0*MH, pHL+0*MH, nullptr, nullptr, 4, 1);
    GArg aA  = GA(pXH+4l*BTC, pXL+4l*BTC, W_L(1), nullptr, pHH+1*MH, pHL+1*MH, nullptr, nullptr, 0, 1);
    GArg aG  = GA(pXH+5l*BTC, pXL+5l*BTC, W_L(2), nullptr, pHH+2*MH, pHL+2*MH, nullptr, nullptr, 5, 1);
    gemm_bf16<<<gNar,256,SMEM_REQ>>>(aW, aW, aW, 128, 1024);
    gemm_bf16<<<gNar,256,SMEM_REQ>>>(aA, aA, aA, 128, 1024);
    gemm_bf16<<<gNar,256,SMEM_REQ>>>(aG, aG, aG, 128, 1024);

    // launch 5: fused R/K/V projections (ncu -s 5 profiles THIS)
    GArg aR = GA(pXH+0l*BTC, pXL+0l*BTC, W_R, pR, nullptr, nullptr, nullptr, nullptr, 0, 0);
    GArg aK = GA(pXH+2l*BTC, pXL+2l*BTC, W_K, pK, nullptr, nullptr, nullptr, nullptr, 0, 0);
    GArg aV = GA(pXH+3l*BTC, pXL+3l*BTC, W_V, pV, nullptr, nullptr, nullptr, nullptr, 0, 0);
    gemm_bf16<<<gRKV,256,SMEM_REQ>>>(aR, aK, aV, 1024, 1024);

    // launch 6: remaining LoRA stage-1 (mv)
    GArg aMV = GA(pXH+3l*BTC, pXL+3l*BTC, W_L(3), nullptr, pHH+3*MH, pHL+3*MH, nullptr, nullptr, 0, 1);
    gemm_bf16<<<gNar,256,SMEM_REQ>>>(aMV, aMV, aMV, 128, 1024);

    // LoRA stage-2 (K=128)
    GArg b0 = GA(pHH+0*MH, pHL+0*MH, W_L(4), pWD, nullptr, nullptr, tdecay, nullptr, 1, 0);
    GArg b1 = GA(pHH+1*MH, pHL+1*MH, W_L(5), pA,  nullptr, nullptr, taaaaa, nullptr, 2, 0);
    GArg b2 = GA(pHH+2*MH, pHL+2*MH, W_L(6), pG,  nullptr, nullptr, nullptr, nullptr, 0, 0);
    GArg b3 = GA(pHH+3*MH, pHL+3*MH, W_L(7), pV,  nullptr, nullptr, misc_v, v0, 3, 0);
    gemm_bf16<<<gBig,256,SMEM_REQ>>>(b0, b0, b0, 1024, 128);
    gemm_bf16<<<gBig,256,SMEM_REQ>>>(b1, b1, b1, 1024, 128);
    gemm_bf16<<<gBig,256,SMEM_REQ>>>(b2, b2, b2, 1024, 128);
    gemm_bf16<<<gBig,256,SMEM_REQ>>>(b3, b3, b3, 1024, 128);

    // kk normalize + k update
    kk_kernel<<<(Bb*Tt*Hh)/8, 256>>>(pK, pA, misc_kkk, misc_a, pKK, pK);

    // sequential recurrence
    scan_kernel<<<Bb*Hh, 128>>>(pR, pWD, pK, pV, pKK, pA, pY);

    // groupnorm + bonus + gate -> bf16 planes
    post_kernel<<<(Bb*Tt*Hh)/8, 256>>>(pY, pR, pK, pV, pG, faaaa, ln_w, ln_b);

    // output projection
    GArg aO = GA(pYGH, pYGL, W_O, (float*)d_out, nullptr, nullptr, nullptr, nullptr, 0, 0);
    gemm_bf16<<<gBig,256,SMEM_REQ>>>(aO, aO, aO, 1024, 1024);

    if (out_size >= 2*BTC)
        copy_kernel<<<(BTC/4 + 255)/256, 256>>>(v0, (float*)d_out + BTC, BTC/4);
}

// round 10
// speedup vs baseline: 1.1077x; 1.1077x over previous
#include <cuda_runtime.h>
#include <cuda_bf16.h>
#include <math.h>

#define Bb 8
#define Tt 2048
#define Cc 1024
#define Hh 16
#define Nn 64
#define Mrows 16384
#define BTC 16777216

typedef __nv_bfloat16 bf16;
typedef unsigned long long ull;

// ---------------- fp32 scratch ----------------
__device__ float g_R[BTC], g_K[BTC], g_V[BTC], g_A[BTC], g_G[BTC];
__device__ float g_WD[BTC], g_KK[BTC], g_Y[BTC];

// ---------------- bf16 hi/lo planes ----------------
__device__ __align__(256) bf16 g_XH[6l*BTC];
__device__ __align__(256) bf16 g_XL[6l*BTC];
__device__ __align__(256) bf16 g_WH[5242880];    // packed weights [K,N] padded
__device__ __align__(256) bf16 g_WL[5242880];
__device__ __align__(256) bf16 g_HH[4l*Mrows*128];
__device__ __align__(256) bf16 g_HL[4l*Mrows*128];
__device__ __align__(256) bf16 g_YGH[BTC];
__device__ __align__(256) bf16 g_YGL[BTC];

#define W_R  0
#define W_K  1048576
#define W_V  2097152
#define W_O  3145728
#define W_L(i) (4194304 + (i)*131072)

__device__ __forceinline__ float sigm(float x){ return 1.0f/(1.0f+expf(-x)); }
__device__ __forceinline__ void split2(float v, bf16& h, bf16& l){
    h = __float2bfloat16(v); l = __float2bfloat16(v - __bfloat162float(h));
}

__device__ __forceinline__ void cpa16(unsigned dst, const void* src) {
    asm volatile("cp.async.cg.shared.global [%0], [%1], 16;" :: "r"(dst), "l"(src));
}
__device__ __forceinline__ void cpcommit(){ asm volatile("cp.async.commit_group;"); }
__device__ __forceinline__ void cpwait1(){ asm volatile("cp.async.wait_group 1;"); }

__device__ __forceinline__ void ldmat4(unsigned& r0, unsigned& r1, unsigned& r2, unsigned& r3,
                                       unsigned addr) {
    asm volatile("ldmatrix.sync.aligned.m8n8.x4.shared.b16 {%0,%1,%2,%3}, [%4];"
                 : "=r"(r0), "=r"(r1), "=r"(r2), "=r"(r3) : "r"(addr));
}
__device__ __forceinline__ void ldmat4t(unsigned& r0, unsigned& r1, unsigned& r2, unsigned& r3,
                                        unsigned addr) {
    asm volatile("ldmatrix.sync.aligned.m8n8.x4.trans.shared.b16 {%0,%1,%2,%3}, [%4];"
                 : "=r"(r0), "=r"(r1), "=r"(r2), "=r"(r3) : "r"(addr));
}
__device__ __forceinline__ void mma16816(float* c, const unsigned* a, unsigned b0, unsigned b1) {
    asm volatile("mma.sync.aligned.m16n8k16.row.col.f32.bf16.bf16.f32 "
                 "{%0,%1,%2,%3}, {%4,%5,%6,%7}, {%8,%9}, {%0,%1,%2,%3};"
                 : "+f"(c[0]), "+f"(c[1]), "+f"(c[2]), "+f"(c[3])
                 : "r"(a[0]), "r"(a[1]), "r"(a[2]), "r"(a[3]), "r"(b0), "r"(b1));
}

// packed f32x2
__device__ __forceinline__ ull fma2(ull a, ull b, ull c){
    ull d; asm("fma.rn.f32x2 %0, %1, %2, %3;" : "=l"(d) : "l"(a), "l"(b), "l"(c)); return d;
}
__device__ __forceinline__ ull mul2(ull a, ull b){
    ull d; asm("mul.rn.f32x2 %0, %1, %2;" : "=l"(d) : "l"(a), "l"(b)); return d;
}
__device__ __forceinline__ ull pack2(float x){
    ull d; asm("mov.b64 %0, {%1, %1};" : "=l"(d) : "f"(x)); return d;
}
__device__ __forceinline__ float sum2(ull v){
    float lo, hi; asm("mov.b64 {%0, %1}, %2;" : "=f"(lo), "=f"(hi) : "l"(v)); return lo + hi;
}

// ============================================================================
// prep: mix x with 6 maa vectors, split to bf16 hi/lo planes.
// ============================================================================
__global__ void __launch_bounds__(256) prep_kernel(
    const float* __restrict__ x,
    const float* __restrict__ m0, const float* __restrict__ m1,
    const float* __restrict__ m2, const float* __restrict__ m3,
    const float* __restrict__ m4, const float* __restrict__ m5)
{
    long e = ((long)blockIdx.x*256 + threadIdx.x)*4;
    int r = (int)(e >> 10), c = (int)(e & 1023);
    float4 cur = *(const float4*)(x + e);
    float4 prv = make_float4(0.f,0.f,0.f,0.f);
    if ((r & (Tt-1)) != 0) prv = *(const float4*)(x + e - Cc);
    float d0 = prv.x-cur.x, d1 = prv.y-cur.y, d2 = prv.z-cur.z, d3 = prv.w-cur.w;
    const float* maas[6] = {m0,m1,m2,m3,m4,m5};
    #pragma unroll
    for (int v = 0; v < 6; v++) {
        float4 mv = *(const float4*)(maas[v] + c);
        float a0 = cur.x + d0*mv.x, a1 = cur.y + d1*mv.y;
        float a2 = cur.z + d2*mv.z, a3 = cur.w + d3*mv.w;
        bf16 h0,l0,h1,l1,h2,l2,h3,l3;
        split2(a0,h0,l0); split2(a1,h1,l1); split2(a2,h2,l2); split2(a3,h3,l3);
        long o = (long)v*BTC + e;
        *(__nv_bfloat162*)&g_XH[o]   = __nv_bfloat162(h0,h1);
        *(__nv_bfloat162*)&g_XH[o+2] = __nv_bfloat162(h2,h3);
        *(__nv_bfloat162*)&g_XL[o]   = __nv_bfloat162(l0,l1);
        *(__nv_bfloat162*)&g_XL[o+2] = __nv_bfloat162(l2,l3);
    }
}

// ============================================================================
// wsplit_all: split ALL weights in one launch.
// ============================================================================
struct WPtrs { const float* w[12]; };

__global__ void __launch_bounds__(256) wsplit_all(WPtrs p)
{
    long g = (long)blockIdx.x*256 + threadIdx.x;   // < 5242880
    float v;
    if (g < 4194304) {
        int which = (int)(g >> 20);
        int off = (int)(g & 1048575);
        v = p.w[which][off];
    } else {
        long h = g - 4194304;
        int i = (int)(h >> 17);
        int off = (int)(h & 131071);
        if (i < 4) {              // stage-1: [1024, Nreal] -> padded [1024,128]
            int r = off >> 7, c = off & 127;
            int Nreal = (i==2) ? 128 : ((i==3) ? 32 : 64);
            v = (c < Nreal) ? p.w[4+i][(long)r*Nreal + c] : 0.f;
        } else {                  // stage-2: [Kreal, 1024] -> padded [128,1024]
            int j = i - 4;
            int r = off >> 10, c = off & 1023;
            int Kreal = (j==2) ? 128 : ((j==3) ? 32 : 64);
            v = (r < Kreal) ? p.w[8+j][(long)r*1024 + c] : 0.f;
        }
    }
    bf16 hh, ll; split2(v, hh, ll);
    g_WH[g] = hh; g_WL[g] = ll;
}

// ============================================================================
// mma.sync GEMM: C[M,N] = A[M,K] @ B[K,N], bf16 hi/lo 3-pass, fp32 accum.
// CTA tile 128x128, BK=32, 3-stage cp.async, ONE barrier per k-iter.
// __launch_bounds__(256,2): 2 CTAs/SM (regs<=128, smem 2x111KB fits 228KB).
// 8 warps (2Mx4N), warp tile 64x32. blockIdx.z selects one of 3 GArg sets.
// ============================================================================
#define AST 40
#define BST 136
#define A_PL 10240           // bytes per A plane (128*40*2)
#define B_OFF 20480
#define B_PL 8704            // bytes per B plane (32*136*2)
#define STG 37888
#define SMEM_REQ (3*STG)     // 113664 B -> 2 CTAs/SM

struct GArg {
    const bf16 *Ah, *Al, *Bh, *Bl;
    float* Cf; bf16 *ChH, *ChL;
    const float *bias, *vaux;
    int epi, outmode;
};

__global__ void __launch_bounds__(256,2) gemm_bf16(GArg g0, GArg g1, GArg g2, int N, int K)
{
    extern __shared__ __align__(16) char smem[];
    const unsigned smemU = (unsigned)__cvta_generic_to_shared(smem);

    const GArg ga = (blockIdx.z == 0) ? g0 : ((blockIdx.z == 1) ? g1 : g2);
    const bf16* __restrict__ Ah = ga.Ah;  const bf16* __restrict__ Al = ga.Al;
    const bf16* __restrict__ Bh = ga.Bh;  const bf16* __restrict__ Bl = ga.Bl;

    const int tid  = threadIdx.x;
    const int bm   = blockIdx.y, bn = blockIdx.x;
    const int warp = tid >> 5, lane = tid & 31;
    const int wm   = warp & 1,  wn  = warp >> 1;

    float acc[4][4][4];
    #pragma unroll
    for (int i = 0; i < 4; i++)
        #pragma unroll
        for (int j = 0; j < 4; j++)
            #pragma unroll
            for (int e = 0; e < 4; e++) acc[i][j][e] = 0.f;

    const int aRow  = wm*64 + (lane & 7) + ((lane >> 3) & 1)*8;
    const int aCsel = (lane >> 4)*8;
    const unsigned aBaseOff = (unsigned)(aRow*AST + aCsel)*2;
    const int bKrow = ((lane >> 3) & 1)*8 + (lane & 7);
    const int bNcol = wn*32 + (lane >> 4)*8;
    const unsigned bBaseOff = (unsigned)(bKrow*BST + bNcol)*2;

    const int NIT = K >> 5;

    const int ar = tid >> 2, ac = (tid & 3)*8;
    const int br = tid >> 4, bc = (tid & 15)*8;
    auto issue = [&](int s, int k0) {
        unsigned sb = smemU + s*STG;
        #pragma unroll
        for (int u = 0; u < 2; u++) {
            int r = ar + u*64;
            unsigned so = (unsigned)(r*AST + ac)*2;
            cpa16(sb + so,        Ah + (long)(bm*128 + r)*K + k0 + ac);
            cpa16(sb + A_PL + so, Al + (long)(bm*128 + r)*K + k0 + ac);
            int r2 = br + u*16;
            unsigned so2 = (unsigned)(r2*BST + bc)*2;
            cpa16(sb + B_OFF + so2,        Bh + (long)(k0 + r2)*N + bn*128 + bc);
            cpa16(sb + B_OFF + B_PL + so2, Bl + (long)(k0 + r2)*N + bn*128 + bc);
        }
        cpcommit();
    };

    issue(0, 0);
    issue(1, 32);

    for (int s = 0; s < NIT; s++) {
        cpwait1();              // stage s complete (uniform 1 group/iter incl. empties)
        __syncthreads();        // publish; also fences prior-stage reads before overwrite
        if (s + 2 < NIT) issue((s + 2) % 3, (s + 2)*32); else cpcommit();

        unsigned sb = smemU + (s % 3)*STG;
        unsigned aH = sb + aBaseOff;
        unsigned aL = aH + A_PL;
        unsigned bH = sb + B_OFF + bBaseOff;
        unsigned bL = bH + B_PL;

        #pragma unroll
        for (int ks = 0; ks < 2; ks++) {
            unsigned ah[4][4], al[4][4], bh[2][4], bl[2][4];
            #pragma unroll
            for (int i = 0; i < 4; i++) {
                unsigned off = (unsigned)(i*16*AST + ks*16)*2;
                ldmat4(ah[i][0], ah[i][1], ah[i][2], ah[i][3], aH + off);
                ldmat4(al[i][0], al[i][1], al[i][2], al[i][3], aL + off);
            }
            #pragma unroll
            for (int jj = 0; jj < 2; jj++) {
                unsigned off = (unsigned)(ks*16*BST + jj*16)*2;
                ldmat4t(bh[jj][0], bh[jj][1], bh[jj][2], bh[jj][3], bH + off);
                ldmat4t(bl[jj][0], bl[jj][1], bl[jj][2], bl[jj][3], bL + off);
            }
            #pragma unroll
            for (int i = 0; i < 4; i++)
                #pragma unroll
                for (int j = 0; j < 4; j++) {
                    int jj = j >> 1, sel = (j & 1)*2;
                    mma16816(acc[i][j], ah[i], bh[jj][sel], bh[jj][sel+1]);
                    mma16816(acc[i][j], ah[i], bl[jj][sel], bl[jj][sel+1]);
                    mma16816(acc[i][j], al[i], bh[jj][sel], bh[jj][sel+1]);
                }
        }
    }

    // ---- epilogue ----
    const int g = lane >> 2, q = lane & 3;
    #pragma unroll
    for (int i = 0; i < 4; i++) {
        int r0 = bm*128 + wm*64 + i*16 + g;
        #pragma unroll
        for (int j = 0; j < 4; j++) {
            int col = bn*128 + wn*32 + j*8 + q*2;
            #pragma unroll
            for (int h = 0; h < 2; h++) {
                int row = r0 + h*8;
                long idx = (long)row*N + col;
                float v0 = acc[i][j][h*2], v1 = acc[i][j][h*2+1];
                if (ga.epi == 1) {
                    v0 = expf(-sigm(ga.bias[col]  +v0)*0.60653065971263342f);
                    v1 = expf(-sigm(ga.bias[col+1]+v1)*0.60653065971263342f);
                } else if (ga.epi == 2) {
                    v0 = sigm(ga.bias[col]+v0); v1 = sigm(ga.bias[col+1]+v1);
                } else if (ga.epi == 3) {
                    float s0 = sigm(ga.bias[col]+v0), s1 = sigm(ga.bias[col+1]+v1);
                    float c0 = ga.Cf[idx], c1 = ga.Cf[idx+1];
                    v0 = c0 + (ga.vaux[idx]  -c0)*s0;
                    v1 = c1 + (ga.vaux[idx+1]-c1)*s1;
                } else if (ga.epi == 4) {
                    v0 = tanhf(v0); v1 = tanhf(v1);
                } else if (ga.epi == 5) {
                    v0 = sigm(v0); v1 = sigm(v1);
                }
                if (ga.outmode == 0) {
                    *(float2*)&ga.Cf[idx] = make_float2(v0, v1);
                } else {
                    bf16 h0,l0,h1,l1;
                    split2(v0,h0,l0); split2(v1,h1,l1);
                    *(__nv_bfloat162*)&ga.ChH[idx] = __nv_bfloat162(h0,h1);
                    *(__nv_bfloat162*)&ga.ChL[idx] = __nv_bfloat162(l0,l1);
                }
            }
        }
    }
}

// ============================================================================
// kk normalize + k update.
// ============================================================================
__global__ void kk_kernel(const float* __restrict__ Kin, const float* __restrict__ Aa,
                          const float* __restrict__ mkk, const float* __restrict__ ma,
                          float* __restrict__ KKo, float* __restrict__ K2o)
{
    int gw   = (blockIdx.x*blockDim.x + threadIdx.x) >> 5;
    int lane = threadIdx.x & 31;
    long off = (long)gw*64 + lane*2;
    int  c   = ((gw & (Hh-1))*64) + lane*2;
    float2 kv = *(const float2*)(Kin + off);
    float2 mk = *(const float2*)(mkk + c);
    float kk0 = kv.x*mk.x, kk1 = kv.y*mk.y;
    float ss = kk0*kk0 + kk1*kk1;
    #pragma unroll
    for (int s = 16; s > 0; s >>= 1) ss += __shfl_xor_sync(0xffffffffu, ss, s);
    float inv = 1.0f / fmaxf(sqrtf(ss), 1e-12f);
    *(float2*)(KKo + off) = make_float2(kk0*inv, kk1*inv);
    float2 av  = *(const float2*)(Aa + off);
    float2 mav = *(const float2*)(ma + c);
    *(float2*)(K2o + off) = make_float2(kv.x*(1.f+(av.x-1.f)*mav.x),
                                        kv.y*(1.f+(av.y-1.f)*mav.y));
}

// ============================================================================
// RWKV7 scan: 128 threads per (b,h); thread owns half a state row; f32x2 FMA.
// ============================================================================
__global__ void __launch_bounds__(128) scan_kernel(
    const float* __restrict__ R,  const float* __restrict__ W,
    const float* __restrict__ K2, const float* __restrict__ V,
    const float* __restrict__ KK, const float* __restrict__ Aa,
    float* __restrict__ Y)
{
    const int bh = blockIdx.x;
    const int b  = bh >> 4, hh = bh & 15;
    const int tid  = threadIdx.x;
    const int i    = tid >> 1;
    const int half = tid & 1;
    const int cb   = half*32;
    const long rowbase = (long)b*Tt*Cc + hh*Nn;

    __shared__ __align__(16) float sm[2][6][Nn];

    ull S2[16];
    #pragma unroll
    for (int j = 0; j < 16; j++) S2[j] = 0ull;

    auto loadstage = [&](int q, int t) {
        long idx = rowbase + (long)t*Cc;
        if (tid < 64) {
            sm[q][0][tid] = R[idx+tid];
            sm[q][1][tid] = W[idx+tid];
            sm[q][2][tid] = K2[idx+tid];
        } else {
            int j = tid - 64;
            sm[q][3][j] = V[idx+j];
            float kk = KK[idx+j], a = Aa[idx+j];
            sm[q][4][j] = kk; sm[q][5][j] = kk*a;
        }
    };

    loadstage(0, 0);
    __syncthreads();

    int p = 0;
    for (int t = 0; t < Tt; t++) {
        if (t + 1 < Tt) loadstage(p^1, t+1);
        const ull* r2  = (const ull*)&sm[p][0][cb];
        const ull* w2  = (const ull*)&sm[p][1][cb];
        const ull* k2  = (const ull*)&sm[p][2][cb];
        const ull* kk2 = (const ull*)&sm[p][4][cb];
        const ull* b2  = (const ull*)&sm[p][5][cb];
        const float vi = sm[p][3][i];

        ull sa_a = 0ull, sa_b = 0ull;
        #pragma unroll
        for (int j = 0; j < 16; j += 2) {
            sa_a = fma2(S2[j],   kk2[j],   sa_a);
            sa_b = fma2(S2[j+1], kk2[j+1], sa_b);
        }
        float sa_p = sum2(sa_a) + sum2(sa_b);
        float sa = -(sa_p + __shfl_xor_sync(0xffffffffu, sa_p, 1));

        ull sa2 = pack2(sa), vi2 = pack2(vi);
        ull o_a = 0ull, o_b = 0ull;
        #pragma unroll
        for (int j = 0; j < 16; j += 2) {
            ull t0 = fma2(sa2, b2[j],   mul2(vi2, k2[j]));
            ull t1 = fma2(sa2, b2[j+1], mul2(vi2, k2[j+1]));
            S2[j]   = fma2(S2[j],   w2[j],   t0);
            S2[j+1] = fma2(S2[j+1], w2[j+1], t1);
            o_a = fma2(S2[j],   r2[j],   o_a);
            o_b = fma2(S2[j+1], r2[j+1], o_b);
        }
        float o_p = sum2(o_a) + sum2(o_b);
        float o = o_p + __shfl_xor_sync(0xffffffffu, o_p, 1);
        if (half == 0) Y[rowbase + (long)t*Cc + i] = o;
        __syncthreads();
        p ^= 1;
    }
}

// ============================================================================
// GroupNorm + rkv bonus + gate -> bf16 hi/lo planes.
// ============================================================================
__global__ void post_kernel(const float* __restrict__ Y,  const float* __restrict__ R,
                            const float* __restrict__ K2, const float* __restrict__ V,
                            const float* __restrict__ G,  const float* __restrict__ faaaa,
                            const float* __restrict__ lnw,const float* __restrict__ lnb)
{
    int gw   = (blockIdx.x*blockDim.x + threadIdx.x) >> 5;
    int lane = threadIdx.x & 31;
    long off = (long)gw*64 + lane*2;
    int  c   = ((gw & 15)*64) + lane*2;
    float2 y  = *(const float2*)(Y + off);
    float2 r  = *(const float2*)(R + off);
    float2 k  = *(const float2*)(K2 + off);
    float2 fa = *(const float2*)(faaaa + c);
    float s1 = y.x + y.y;
    float s2 = y.x*y.x + y.y*y.y;
    float rk = r.x*k.x*fa.x + r.y*k.y*fa.y;
    #pragma unroll
    for (int s = 16; s > 0; s >>= 1) {
        s1 += __shfl_xor_sync(0xffffffffu, s1, s);
        s2 += __shfl_xor_sync(0xffffffffu, s2, s);
        rk += __shfl_xor_sync(0xffffffffu, rk, s);
    }
    float mu  = s1 * (1.0f/64.0f);
    float var = s2 * (1.0f/64.0f) - mu*mu;
    float rs  = rsqrtf(var + 6.4e-4f);
    float2 w2 = *(const float2*)(lnw + c);
    float2 b2 = *(const float2*)(lnb + c);
    float2 v  = *(const float2*)(V + off);
    float2 g  = *(const float2*)(G + off);
    float o0 = ((y.x-mu)*rs*w2.x + b2.x + rk*v.x) * g.x;
    float o1 = ((y.y-mu)*rs*w2.y + b2.y + rk*v.y) * g.y;
    bf16 h0,l0,h1,l1;
    split2(o0,h0,l0); split2(o1,h1,l1);
    *(__nv_bfloat162*)&g_YGH[off] = __nv_bfloat162(h0,h1);
    *(__nv_bfloat162*)&g_YGL[off] = __nv_bfloat162(l0,l1);
}

__global__ void copy_kernel(const float* __restrict__ src, float* __restrict__ dst, int n4)
{
    int idx = blockIdx.x*blockDim.x + threadIdx.x;
    if (idx < n4) ((float4*)dst)[idx] = ((const float4*)src)[idx];
}

// ============================================================================
extern "C" void kernel_launch(void* const* d_in, const int* in_sizes, int n_in,
                              void* d_out, int out_size)
{
    const float* x        = (const float*)d_in[0];
    const float* v0       = (const float*)d_in[1];
    const float* maa_r    = (const float*)d_in[2];
    const float* maa_w    = (const float*)d_in[3];
    const float* maa_k    = (const float*)d_in[4];
    const float* maa_v    = (const float*)d_in[5];
    const float* maa_a    = (const float*)d_in[6];
    const float* maa_g    = (const float*)d_in[7];
    const float* tdecay   = (const float*)d_in[8];
    const float* faaaa    = (const float*)d_in[9];
    const float* taaaaa   = (const float*)d_in[10];
    const float* decay_w1 = (const float*)d_in[11];
    const float* decay_w2 = (const float*)d_in[12];
    const float* aaa_w1   = (const float*)d_in[13];
    const float* aaa_w2   = (const float*)d_in[14];
    const float* gate_w1  = (const float*)d_in[15];
    const float* gate_w2  = (const float*)d_in[16];
    const float* mv_w1    = (const float*)d_in[17];
    const float* mv_w2    = (const float*)d_in[18];
    const float* misc_v   = (const float*)d_in[19];
    const float* misc_kkk = (const float*)d_in[20];
    const float* misc_a   = (const float*)d_in[21];
    const float* W_r      = (const float*)d_in[22];
    const float* W_k      = (const float*)d_in[23];
    const float* W_v      = (const float*)d_in[24];
    const float* W_out    = (const float*)d_in[25];
    const float* ln_w     = (const float*)d_in[26];
    const float* ln_b     = (const float*)d_in[27];

    static float *pR=nullptr,*pK,*pV,*pA,*pG,*pWD,*pKK,*pY;
    static bf16 *pXH,*pXL,*pWH,*pWL,*pHH,*pHL,*pYGH,*pYGL;
    if (!pR) {
        cudaGetSymbolAddress((void**)&pR,  g_R);
        cudaGetSymbolAddress((void**)&pK,  g_K);
        cudaGetSymbolAddress((void**)&pV,  g_V);
        cudaGetSymbolAddress((void**)&pA,  g_A);
        cudaGetSymbolAddress((void**)&pG,  g_G);
        cudaGetSymbolAddress((void**)&pWD, g_WD);
        cudaGetSymbolAddress((void**)&pKK, g_KK);
        cudaGetSymbolAddress((void**)&pY,  g_Y);
        cudaGetSymbolAddress((void**)&pXH, g_XH);
        cudaGetSymbolAddress((void**)&pXL, g_XL);
        cudaGetSymbolAddress((void**)&pWH, g_WH);
        cudaGetSymbolAddress((void**)&pWL, g_WL);
        cudaGetSymbolAddress((void**)&pHH, g_HH);
        cudaGetSymbolAddress((void**)&pHL, g_HL);
        cudaGetSymbolAddress((void**)&pYGH, g_YGH);
        cudaGetSymbolAddress((void**)&pYGL, g_YGL);
        cudaFuncSetAttribute(gemm_bf16, cudaFuncAttributeMaxDynamicSharedMemorySize, SMEM_REQ);
    }

    const long MH = (long)Mrows*128;
    auto GA = [&](const bf16* Ah, const bf16* Al, long wOff,
                  float* Cf, bf16* ChH, bf16* ChL,
                  const float* bias, const float* vaux, int epi, int outmode) {
        GArg a;
        a.Ah = Ah; a.Al = Al; a.Bh = pWH + wOff; a.Bl = pWL + wOff;
        a.Cf = Cf; a.ChH = ChH; a.ChL = ChL;
        a.bias = bias; a.vaux = vaux; a.epi = epi; a.outmode = outmode;
        return a;
    };

    // launch 0: prep
    prep_kernel<<<BTC/1024, 256>>>(x, maa_r, maa_w, maa_k, maa_v, maa_a, maa_g);

    // launch 1: all weight splits fused
    WPtrs wp;
    wp.w[0]=W_r; wp.w[1]=W_k; wp.w[2]=W_v; wp.w[3]=W_out;
    wp.w[4]=decay_w1; wp.w[5]=aaa_w1; wp.w[6]=gate_w1; wp.w[7]=mv_w1;
    wp.w[8]=decay_w2; wp.w[9]=aaa_w2; wp.w[10]=gate_w2; wp.w[11]=mv_w2;
    wsplit_all<<<20480, 256>>>(wp);

    dim3 gBig(8, 128, 1), gRKV(8, 128, 3), gNar(1, 128, 1);

    // launches 2-4: three LoRA stage-1 GEMMs (N=128, K=1024)
    GArg aW  = GA(pXH+1l*BTC, pXL+1l*BTC, W_L(0), nullptr, pHH+0*MH, pHL+0*MH, nullptr, nullptr, 4, 1);
    GArg aA  = GA(pXH+4l*BTC, pXL+4l*BTC, W_L(1), nullptr, pHH+1*MH, pHL+1*MH, nullptr, nullptr, 0, 1);
    GArg aG  = GA(pXH+5l*BTC, pXL+5l*BTC, W_L(2), nullptr, pHH+2*MH, pHL+2*MH, nullptr, nullptr, 5, 1);
    gemm_bf16<<<gNar,256,SMEM_REQ>>>(aW, aW, aW, 128, 1024);
    gemm_bf16<<<gNar,256,SMEM_REQ>>>(aA, aA, aA, 128, 1024);
    gemm_bf16<<<gNar,256,SMEM_REQ>>>(aG, aG, aG, 128, 1024);

    // launch 5: fused R/K/V projections (ncu -s 5 profiles THIS)
    GArg aR = GA(pXH+0l*BTC, pXL+0l*BTC, W_R, pR, nullptr, nullptr, nullptr, nullptr, 0, 0);
    GArg aK = GA(pXH+2l*BTC, pXL+2l*BTC, W_K, pK, nullptr, nullptr, nullptr, nullptr, 0, 0);
    GArg aV = GA(pXH+3l*BTC, pXL+3l*BTC, W_V, pV, nullptr, nullptr, nullptr, nullptr, 0, 0);
    gemm_bf16<<<gRKV,256,SMEM_REQ>>>(aR, aK, aV, 1024, 1024);

    // launch 6: remaining LoRA stage-1 (mv)
    GArg aMV = GA(pXH+3l*BTC, pXL+3l*BTC, W_L(3), nullptr, pHH+3*MH, pHL+3*MH, nullptr, nullptr, 0, 1);
    gemm_bf16<<<gNar,256,SMEM_REQ>>>(aMV, aMV, aMV, 128, 1024);

    // LoRA stage-2 (K=128)
    GArg b0 = GA(pHH+0*MH, pHL+0*MH, W_L(4), pWD, nullptr, nullptr, tdecay, nullptr, 1, 0);
    GArg b1 = GA(pHH+1*MH, pHL+1*MH, W_L(5), pA,  nullptr, nullptr, taaaaa, nullptr, 2, 0);
    GArg b2 = GA(pHH+2*MH, pHL+2*MH, W_L(6), pG,  nullptr, nullptr, nullptr, nullptr, 0, 0);
    GArg b3 = GA(pHH+3*MH, pHL+3*MH, W_L(7), pV,  nullptr, nullptr, misc_v, v0, 3, 0);
    gemm_bf16<<<gBig,256,SMEM_REQ>>>(b0, b0, b0, 1024, 128);
    gemm_bf16<<<gBig,256,SMEM_REQ>>>(b1, b1, b1, 1024, 128);
    gemm_bf16<<<gBig,256,SMEM_REQ>>>(b2, b2, b2, 1024, 128);
    gemm_bf16<<<gBig,256,SMEM_REQ>>>(b3, b3, b3, 1024, 128);

    // kk normalize + k update
    kk_kernel<<<(Bb*Tt*Hh)/8, 256>>>(pK, pA, misc_kkk, misc_a, pKK, pK);

    // sequential recurrence
    scan_kernel<<<Bb*Hh, 128>>>(pR, pWD, pK, pV, pKK, pA, pY);

    // groupnorm + bonus + gate -> bf16 planes
    post_kernel<<<(Bb*Tt*Hh)/8, 256>>>(pY, pR, pK, pV, pG, faaaa, ln_w, ln_b);

    // output projection
    GArg aO = GA(pYGH, pYGL, W_O, (float*)d_out, nullptr, nullptr, nullptr, nullptr, 0, 0);
    gemm_bf16<<<gBig,256,SMEM_REQ>>>(aO, aO, aO, 1024, 1024);

    if (out_size >= 2*BTC)
        copy_kernel<<<(BTC/4 + 255)/256, 256>>>(v0, (float*)d_out + BTC, BTC/4);
}

// round 12
// speedup vs baseline: 1.1432x; 1.0321x over previous
#include <cuda_runtime.h>
#include <cuda_bf16.h>
#include <math.h>

#define Bb 8
#define Tt 2048
#define Cc 1024
#define Hh 16
#define Nn 64
#define Mrows 16384
#define BTC 16777216

typedef __nv_bfloat16 bf16;
typedef unsigned long long ull;

// ---------------- fp32 scratch ----------------
__device__ float g_R[BTC], g_K[BTC], g_V[BTC], g_A[BTC], g_G[BTC];
__device__ float g_WD[BTC], g_KK[BTC], g_Y[BTC];

// ---------------- bf16 hi/lo planes ----------------
__device__ __align__(256) bf16 g_XH[6l*BTC];
__device__ __align__(256) bf16 g_XL[6l*BTC];
__device__ __align__(256) bf16 g_WH[5242880];    // packed weights [K,N] padded
__device__ __align__(256) bf16 g_WL[5242880];
__device__ __align__(256) bf16 g_HH[4l*Mrows*128];
__device__ __align__(256) bf16 g_HL[4l*Mrows*128];
__device__ __align__(256) bf16 g_YGH[BTC];
__device__ __align__(256) bf16 g_YGL[BTC];

#define W_R  0
#define W_K  1048576
#define W_V  2097152
#define W_O  3145728
#define W_L(i) (4194304 + (i)*131072)

__device__ __forceinline__ float sigm(float x){ return 1.0f/(1.0f+expf(-x)); }
__device__ __forceinline__ void split2(float v, bf16& h, bf16& l){
    h = __float2bfloat16(v); l = __float2bfloat16(v - __bfloat162float(h));
}

__device__ __forceinline__ void cpa16(unsigned dst, const void* src) {
    asm volatile("cp.async.cg.shared.global [%0], [%1], 16;" :: "r"(dst), "l"(src));
}
__device__ __forceinline__ void cpcommit(){ asm volatile("cp.async.commit_group;"); }
__device__ __forceinline__ void cpwait1(){ asm volatile("cp.async.wait_group 1;"); }

__device__ __forceinline__ void ldmat4(unsigned& r0, unsigned& r1, unsigned& r2, unsigned& r3,
                                       unsigned addr) {
    asm volatile("ldmatrix.sync.aligned.m8n8.x4.shared.b16 {%0,%1,%2,%3}, [%4];"
                 : "=r"(r0), "=r"(r1), "=r"(r2), "=r"(r3) : "r"(addr));
}
__device__ __forceinline__ void ldmat4t(unsigned& r0, unsigned& r1, unsigned& r2, unsigned& r3,
                                        unsigned addr) {
    asm volatile("ldmatrix.sync.aligned.m8n8.x4.trans.shared.b16 {%0,%1,%2,%3}, [%4];"
                 : "=r"(r0), "=r"(r1), "=r"(r2), "=r"(r3) : "r"(addr));
}
__device__ __forceinline__ void mma16816(float* c, const unsigned* a, unsigned b0, unsigned b1) {
    asm volatile("mma.sync.aligned.m16n8k16.row.col.f32.bf16.bf16.f32 "
                 "{%0,%1,%2,%3}, {%4,%5,%6,%7}, {%8,%9}, {%0,%1,%2,%3};"
                 : "+f"(c[0]), "+f"(c[1]), "+f"(c[2]), "+f"(c[3])
                 : "r"(a[0]), "r"(a[1]), "r"(a[2]), "r"(a[3]), "r"(b0), "r"(b1));
}

// packed f32x2
__device__ __forceinline__ ull fma2(ull a, ull b, ull c){
    ull d; asm("fma.rn.f32x2 %0, %1, %2, %3;" : "=l"(d) : "l"(a), "l"(b), "l"(c)); return d;
}
__device__ __forceinline__ ull mul2(ull a, ull b){
    ull d; asm("mul.rn.f32x2 %0, %1, %2;" : "=l"(d) : "l"(a), "l"(b)); return d;
}
__device__ __forceinline__ ull pack2(float x){
    ull d; asm("mov.b64 %0, {%1, %1};" : "=l"(d) : "f"(x)); return d;
}
__device__ __forceinline__ float sum2(ull v){
    float lo, hi; asm("mov.b64 {%0, %1}, %2;" : "=f"(lo), "=f"(hi) : "l"(v)); return lo + hi;
}

// ============================================================================
// prep: mix x with 6 maa vectors, split to bf16 hi/lo planes.
// ============================================================================
__global__ void __launch_bounds__(256) prep_kernel(
    const float* __restrict__ x,
    const float* __restrict__ m0, const float* __restrict__ m1,
    const float* __restrict__ m2, const float* __restrict__ m3,
    const float* __restrict__ m4, const float* __restrict__ m5)
{
    long e = ((long)blockIdx.x*256 + threadIdx.x)*4;
    int r = (int)(e >> 10), c = (int)(e & 1023);
    float4 cur = *(const float4*)(x + e);
    float4 prv = make_float4(0.f,0.f,0.f,0.f);
    if ((r & (Tt-1)) != 0) prv = *(const float4*)(x + e - Cc);
    float d0 = prv.x-cur.x, d1 = prv.y-cur.y, d2 = prv.z-cur.z, d3 = prv.w-cur.w;
    const float* maas[6] = {m0,m1,m2,m3,m4,m5};
    #pragma unroll
    for (int v = 0; v < 6; v++) {
        float4 mv = *(const float4*)(maas[v] + c);
        float a0 = cur.x + d0*mv.x, a1 = cur.y + d1*mv.y;
        float a2 = cur.z + d2*mv.z, a3 = cur.w + d3*mv.w;
        bf16 h0,l0,h1,l1,h2,l2,h3,l3;
        split2(a0,h0,l0); split2(a1,h1,l1); split2(a2,h2,l2); split2(a3,h3,l3);
        long o = (long)v*BTC + e;
        *(__nv_bfloat162*)&g_XH[o]   = __nv_bfloat162(h0,h1);
        *(__nv_bfloat162*)&g_XH[o+2] = __nv_bfloat162(h2,h3);
        *(__nv_bfloat162*)&g_XL[o]   = __nv_bfloat162(l0,l1);
        *(__nv_bfloat162*)&g_XL[o+2] = __nv_bfloat162(l2,l3);
    }
}

// ============================================================================
// wsplit_all: split ALL weights in one launch.
// ============================================================================
struct WPtrs { const float* w[12]; };

__global__ void __launch_bounds__(256) wsplit_all(WPtrs p)
{
    long g = (long)blockIdx.x*256 + threadIdx.x;   // < 5242880
    float v;
    if (g < 4194304) {
        int which = (int)(g >> 20);
        int off = (int)(g & 1048575);
        v = p.w[which][off];
    } else {
        long h = g - 4194304;
        int i = (int)(h >> 17);
        int off = (int)(h & 131071);
        if (i < 4) {              // stage-1: [1024, Nreal] -> padded [1024,128]
            int r = off >> 7, c = off & 127;
            int Nreal = (i==2) ? 128 : ((i==3) ? 32 : 64);
            v = (c < Nreal) ? p.w[4+i][(long)r*Nreal + c] : 0.f;
        } else {                  // stage-2: [Kreal, 1024] -> padded [128,1024]
            int j = i - 4;
            int r = off >> 10, c = off & 1023;
            int Kreal = (j==2) ? 128 : ((j==3) ? 32 : 64);
            v = (r < Kreal) ? p.w[8+j][(long)r*1024 + c] : 0.f;
        }
    }
    bf16 hh, ll; split2(v, hh, ll);
    g_WH[g] = hh; g_WL[g] = ll;
}

// ============================================================================
// mma.sync GEMM: C[M,N] = A[M,K] @ B[K,N], bf16 hi/lo 3-pass, fp32 accum.
// CTA tile 128x128, BK=32, 3-stage cp.async, ONE barrier per k-iter.
// __launch_bounds__(256,2). blockIdx.z selects one of 4 GArg sets.
// Inner loop interleaves ldmatrix batches with MMA passes.
// ============================================================================
#define AST 40
#define BST 136
#define A_PL 10240           // bytes per A plane (128*40*2)
#define B_OFF 20480
#define B_PL 8704            // bytes per B plane (32*136*2)
#define STG 37888
#define SMEM_REQ (3*STG)     // 113664 B -> 2 CTAs/SM

struct GArg {
    const bf16 *Ah, *Al, *Bh, *Bl;
    float* Cf; bf16 *ChH, *ChL;
    const float *bias, *vaux;
    int epi, outmode;
};

__global__ void __launch_bounds__(256,2) gemm_bf16(GArg g0, GArg g1, GArg g2, GArg g3,
                                                   int N, int K)
{
    extern __shared__ __align__(16) char smem[];
    const unsigned smemU = (unsigned)__cvta_generic_to_shared(smem);

    const int bz = blockIdx.z;
    const GArg ga = (bz == 0) ? g0 : ((bz == 1) ? g1 : ((bz == 2) ? g2 : g3));
    const bf16* __restrict__ Ah = ga.Ah;  const bf16* __restrict__ Al = ga.Al;
    const bf16* __restrict__ Bh = ga.Bh;  const bf16* __restrict__ Bl = ga.Bl;

    const int tid  = threadIdx.x;
    const int bm   = blockIdx.y, bn = blockIdx.x;
    const int warp = tid >> 5, lane = tid & 31;
    const int wm   = warp & 1,  wn  = warp >> 1;

    float acc[4][4][4];
    #pragma unroll
    for (int i = 0; i < 4; i++)
        #pragma unroll
        for (int j = 0; j < 4; j++)
            #pragma unroll
            for (int e = 0; e < 4; e++) acc[i][j][e] = 0.f;

    const int aRow  = wm*64 + (lane & 7) + ((lane >> 3) & 1)*8;
    const int aCsel = (lane >> 4)*8;
    const unsigned aBaseOff = (unsigned)(aRow*AST + aCsel)*2;
    const int bKrow = ((lane >> 3) & 1)*8 + (lane & 7);
    const int bNcol = wn*32 + (lane >> 4)*8;
    const unsigned bBaseOff = (unsigned)(bKrow*BST + bNcol)*2;

    const int NIT = K >> 5;

    const int ar = tid >> 2, ac = (tid & 3)*8;
    const int br = tid >> 4, bc = (tid & 15)*8;
    auto issue = [&](int s, int k0) {
        unsigned sb = smemU + s*STG;
        #pragma unroll
        for (int u = 0; u < 2; u++) {
            int r = ar + u*64;
            unsigned so = (unsigned)(r*AST + ac)*2;
            cpa16(sb + so,        Ah + (long)(bm*128 + r)*K + k0 + ac);
            cpa16(sb + A_PL + so, Al + (long)(bm*128 + r)*K + k0 + ac);
            int r2 = br + u*16;
            unsigned so2 = (unsigned)(r2*BST + bc)*2;
            cpa16(sb + B_OFF + so2,        Bh + (long)(k0 + r2)*N + bn*128 + bc);
            cpa16(sb + B_OFF + B_PL + so2, Bl + (long)(k0 + r2)*N + bn*128 + bc);
        }
        cpcommit();
    };

    issue(0, 0);
    issue(1, 32);

    for (int s = 0; s < NIT; s++) {
        cpwait1();
        __syncthreads();
        if (s + 2 < NIT) issue((s + 2) % 3, (s + 2)*32); else cpcommit();

        unsigned sb = smemU + (s % 3)*STG;
        unsigned aH = sb + aBaseOff;
        unsigned aL = aH + A_PL;
        unsigned bH = sb + B_OFF + bBaseOff;
        unsigned bL = bH + B_PL;

        #pragma unroll
        for (int ks = 0; ks < 2; ks++) {
            unsigned ah[4][4], al[4][4], bh[2][4], bl[2][4];
            // batch 1: ah, bh, al in flight
            #pragma unroll
            for (int i = 0; i < 4; i++) {
                unsigned off = (unsigned)(i*16*AST + ks*16)*2;
                ldmat4(ah[i][0], ah[i][1], ah[i][2], ah[i][3], aH + off);
            }
            #pragma unroll
            for (int jj = 0; jj < 2; jj++) {
                unsigned off = (unsigned)(ks*16*BST + jj*16)*2;
                ldmat4t(bh[jj][0], bh[jj][1], bh[jj][2], bh[jj][3], bH + off);
            }
            #pragma unroll
            for (int i = 0; i < 4; i++) {
                unsigned off = (unsigned)(i*16*AST + ks*16)*2;
                ldmat4(al[i][0], al[i][1], al[i][2], al[i][3], aL + off);
            }
            // pass 1: ah*bh (covers al loads)
            #pragma unroll
            for (int i = 0; i < 4; i++)
                #pragma unroll
                for (int j = 0; j < 4; j++) {
                    int jj = j >> 1, sel = (j & 1)*2;
                    mma16816(acc[i][j], ah[i], bh[jj][sel], bh[jj][sel+1]);
                }
            // issue bl loads, covered by pass 3
            #pragma unroll
            for (int jj = 0; jj < 2; jj++) {
                unsigned off = (unsigned)(ks*16*BST + jj*16)*2;
                ldmat4t(bl[jj][0], bl[jj][1], bl[jj][2], bl[jj][3], bL + off);
            }
            // pass 3: al*bh
            #pragma unroll
            for (int i = 0; i < 4; i++)
                #pragma unroll
                for (int j = 0; j < 4; j++) {
                    int jj = j >> 1, sel = (j & 1)*2;
                    mma16816(acc[i][j], al[i], bh[jj][sel], bh[jj][sel+1]);
                }
            // pass 2: ah*bl
            #pragma unroll
            for (int i = 0; i < 4; i++)
                #pragma unroll
                for (int j = 0; j < 4; j++) {
                    int jj = j >> 1, sel = (j & 1)*2;
                    mma16816(acc[i][j], ah[i], bl[jj][sel], bl[jj][sel+1]);
                }
        }
    }

    // ---- epilogue ----
    const int g = lane >> 2, q = lane & 3;
    #pragma unroll
    for (int i = 0; i < 4; i++) {
        int r0 = bm*128 + wm*64 + i*16 + g;
        #pragma unroll
        for (int j = 0; j < 4; j++) {
            int col = bn*128 + wn*32 + j*8 + q*2;
            #pragma unroll
            for (int h = 0; h < 2; h++) {
                int row = r0 + h*8;
                long idx = (long)row*N + col;
                float v0 = acc[i][j][h*2], v1 = acc[i][j][h*2+1];
                if (ga.epi == 1) {
                    v0 = expf(-sigm(ga.bias[col]  +v0)*0.60653065971263342f);
                    v1 = expf(-sigm(ga.bias[col+1]+v1)*0.60653065971263342f);
                } else if (ga.epi == 2) {
                    v0 = sigm(ga.bias[col]+v0); v1 = sigm(ga.bias[col+1]+v1);
                } else if (ga.epi == 3) {
                    float s0 = sigm(ga.bias[col]+v0), s1 = sigm(ga.bias[col+1]+v1);
                    float c0 = ga.Cf[idx], c1 = ga.Cf[idx+1];
                    v0 = c0 + (ga.vaux[idx]  -c0)*s0;
                    v1 = c1 + (ga.vaux[idx+1]-c1)*s1;
                } else if (ga.epi == 4) {
                    v0 = tanhf(v0); v1 = tanhf(v1);
                } else if (ga.epi == 5) {
                    v0 = sigm(v0); v1 = sigm(v1);
                }
                if (ga.outmode == 0) {
                    *(float2*)&ga.Cf[idx] = make_float2(v0, v1);
                } else {
                    bf16 h0,l0,h1,l1;
                    split2(v0,h0,l0); split2(v1,h1,l1);
                    *(__nv_bfloat162*)&ga.ChH[idx] = __nv_bfloat162(h0,h1);
                    *(__nv_bfloat162*)&ga.ChL[idx] = __nv_bfloat162(l0,l1);
                }
            }
        }
    }
}

// ============================================================================
// kk normalize + k update.
// ============================================================================
__global__ void kk_kernel(const float* __restrict__ Kin, const float* __restrict__ Aa,
                          const float* __restrict__ mkk, const float* __restrict__ ma,
                          float* __restrict__ KKo, float* __restrict__ K2o)
{
    int gw   = (blockIdx.x*blockDim.x + threadIdx.x) >> 5;
    int lane = threadIdx.x & 31;
    long off = (long)gw*64 + lane*2;
    int  c   = ((gw & (Hh-1))*64) + lane*2;
    float2 kv = *(const float2*)(Kin + off);
    float2 mk = *(const float2*)(mkk + c);
    float kk0 = kv.x*mk.x, kk1 = kv.y*mk.y;
    float ss = kk0*kk0 + kk1*kk1;
    #pragma unroll
    for (int s = 16; s > 0; s >>= 1) ss += __shfl_xor_sync(0xffffffffu, ss, s);
    float inv = 1.0f / fmaxf(sqrtf(ss), 1e-12f);
    *(float2*)(KKo + off) = make_float2(kk0*inv, kk1*inv);
    float2 av  = *(const float2*)(Aa + off);
    float2 mav = *(const float2*)(ma + c);
    *(float2*)(K2o + off) = make_float2(kv.x*(1.f+(av.x-1.f)*mav.x),
                                        kv.y*(1.f+(av.y-1.f)*mav.y));
}

// ============================================================================
// RWKV7 scan: 128 threads per (b,h); thread owns half a state row; f32x2 FMA.
// ============================================================================
__global__ void __launch_bounds__(128) scan_kernel(
    const float* __restrict__ R,  const float* __restrict__ W,
    const float* __restrict__ K2, const float* __restrict__ V,
    const float* __restrict__ KK, const float* __restrict__ Aa,
    float* __restrict__ Y)
{
    const int bh = blockIdx.x;
    const int b  = bh >> 4, hh = bh & 15;
    const int tid  = threadIdx.x;
    const int i    = tid >> 1;
    const int half = tid & 1;
    const int cb   = half*32;
    const long rowbase = (long)b*Tt*Cc + hh*Nn;

    __shared__ __align__(16) float sm[2][6][Nn];

    ull S2[16];
    #pragma unroll
    for (int j = 0; j < 16; j++) S2[j] = 0ull;

    auto loadstage = [&](int q, int t) {
        long idx = rowbase + (long)t*Cc;
        if (tid < 64) {
            sm[q][0][tid] = R[idx+tid];
            sm[q][1][tid] = W[idx+tid];
            sm[q][2][tid] = K2[idx+tid];
        } else {
            int j = tid - 64;
            sm[q][3][j] = V[idx+j];
            float kk = KK[idx+j], a = Aa[idx+j];
            sm[q][4][j] = kk; sm[q][5][j] = kk*a;
        }
    };

    loadstage(0, 0);
    __syncthreads();

    int p = 0;
    for (int t = 0; t < Tt; t++) {
        if (t + 1 < Tt) loadstage(p^1, t+1);
        const ull* r2  = (const ull*)&sm[p][0][cb];
        const ull* w2  = (const ull*)&sm[p][1][cb];
        const ull* k2  = (const ull*)&sm[p][2][cb];
        const ull* kk2 = (const ull*)&sm[p][4][cb];
        const ull* b2  = (const ull*)&sm[p][5][cb];
        const float vi = sm[p][3][i];

        ull sa_a = 0ull, sa_b = 0ull;
        #pragma unroll
        for (int j = 0; j < 16; j += 2) {
            sa_a = fma2(S2[j],   kk2[j],   sa_a);
            sa_b = fma2(S2[j+1], kk2[j+1], sa_b);
        }
        float sa_p = sum2(sa_a) + sum2(sa_b);
        float sa = -(sa_p + __shfl_xor_sync(0xffffffffu, sa_p, 1));

        ull sa2 = pack2(sa), vi2 = pack2(vi);
        ull o_a = 0ull, o_b = 0ull;
        #pragma unroll
        for (int j = 0; j < 16; j += 2) {
            ull t0 = fma2(sa2, b2[j],   mul2(vi2, k2[j]));
            ull t1 = fma2(sa2, b2[j+1], mul2(vi2, k2[j+1]));
            S2[j]   = fma2(S2[j],   w2[j],   t0);
            S2[j+1] = fma2(S2[j+1], w2[j+1], t1);
            o_a = fma2(S2[j],   r2[j],   o_a);
            o_b = fma2(S2[j+1], r2[j+1], o_b);
        }
        float o_p = sum2(o_a) + sum2(o_b);
        float o = o_p + __shfl_xor_sync(0xffffffffu, o_p, 1);
        if (half == 0) Y[rowbase + (long)t*Cc + i] = o;
        __syncthreads();
        p ^= 1;
    }
}

// ============================================================================
// GroupNorm + rkv bonus + gate -> bf16 hi/lo planes.
// ============================================================================
__global__ void post_kernel(const float* __restrict__ Y,  const float* __restrict__ R,
                            const float* __restrict__ K2, const float* __restrict__ V,
                            const float* __restrict__ G,  const float* __restrict__ faaaa,
                            const float* __restrict__ lnw,const float* __restrict__ lnb)
{
    int gw   = (blockIdx.x*blockDim.x + threadIdx.x) >> 5;
    int lane = threadIdx.x & 31;
    long off = (long)gw*64 + lane*2;
    int  c   = ((gw & 15)*64) + lane*2;
    float2 y  = *(const float2*)(Y + off);
    float2 r  = *(const float2*)(R + off);
    float2 k  = *(const float2*)(K2 + off);
    float2 fa = *(const float2*)(faaaa + c);
    float s1 = y.x + y.y;
    float s2 = y.x*y.x + y.y*y.y;
    float rk = r.x*k.x*fa.x + r.y*k.y*fa.y;
    #pragma unroll
    for (int s = 16; s > 0; s >>= 1) {
        s1 += __shfl_xor_sync(0xffffffffu, s1, s);
        s2 += __shfl_xor_sync(0xffffffffu, s2, s);
        rk += __shfl_xor_sync(0xffffffffu, rk, s);
    }
    float mu  = s1 * (1.0f/64.0f);
    float var = s2 * (1.0f/64.0f) - mu*mu;
    float rs  = rsqrtf(var + 6.4e-4f);
    float2 w2 = *(const float2*)(lnw + c);
    float2 b2 = *(const float2*)(lnb + c);
    float2 v  = *(const float2*)(V + off);
    float2 g  = *(const float2*)(G + off);
    float o0 = ((y.x-mu)*rs*w2.x + b2.x + rk*v.x) * g.x;
    float o1 = ((y.y-mu)*rs*w2.y + b2.y + rk*v.y) * g.y;
    bf16 h0,l0,h1,l1;
    split2(o0,h0,l0); split2(o1,h1,l1);
    *(__nv_bfloat162*)&g_YGH[off] = __nv_bfloat162(h0,h1);
    *(__nv_bfloat162*)&g_YGL[off] = __nv_bfloat162(l0,l1);
}

__global__ void copy_kernel(const float* __restrict__ src, float* __restrict__ dst, int n4)
{
    int idx = blockIdx.x*blockDim.x + threadIdx.x;
    if (idx < n4) ((float4*)dst)[idx] = ((const float4*)src)[idx];
}

// ============================================================================
extern "C" void kernel_launch(void* const* d_in, const int* in_sizes, int n_in,
                              void* d_out, int out_size)
{
    const float* x        = (const float*)d_in[0];
    const float* v0       = (const float*)d_in[1];
    const float* maa_r    = (const float*)d_in[2];
    const float* maa_w    = (const float*)d_in[3];
    const float* maa_k    = (const float*)d_in[4];
    const float* maa_v    = (const float*)d_in[5];
    const float* maa_a    = (const float*)d_in[6];
    const float* maa_g    = (const float*)d_in[7];
    const float* tdecay   = (const float*)d_in[8];
    const float* faaaa    = (const float*)d_in[9];
    const float* taaaaa   = (const float*)d_in[10];
    const float* decay_w1 = (const float*)d_in[11];
    const float* decay_w2 = (const float*)d_in[12];
    const float* aaa_w1   = (const float*)d_in[13];
    const float* aaa_w2   = (const float*)d_in[14];
    const float* gate_w1  = (const float*)d_in[15];
    const float* gate_w2  = (const float*)d_in[16];
    const float* mv_w1    = (const float*)d_in[17];
    const float* mv_w2    = (const float*)d_in[18];
    const float* misc_v   = (const float*)d_in[19];
    const float* misc_kkk = (const float*)d_in[20];
    const float* misc_a   = (const float*)d_in[21];
    const float* W_r      = (const float*)d_in[22];
    const float* W_k      = (const float*)d_in[23];
    const float* W_v      = (const float*)d_in[24];
    const float* W_out    = (const float*)d_in[25];
    const float* ln_w     = (const float*)d_in[26];
    const float* ln_b     = (const float*)d_in[27];

    static float *pR=nullptr,*pK,*pV,*pA,*pG,*pWD,*pKK,*pY;
    static bf16 *pXH,*pXL,*pWH,*pWL,*pHH,*pHL,*pYGH,*pYGL;
    if (!pR) {
        cudaGetSymbolAddress((void**)&pR,  g_R);
        cudaGetSymbolAddress((void**)&pK,  g_K);
        cudaGetSymbolAddress((void**)&pV,  g_V);
        cudaGetSymbolAddress((void**)&pA,  g_A);
        cudaGetSymbolAddress((void**)&pG,  g_G);
        cudaGetSymbolAddress((void**)&pWD, g_WD);
        cudaGetSymbolAddress((void**)&pKK, g_KK);
        cudaGetSymbolAddress((void**)&pY,  g_Y);
        cudaGetSymbolAddress((void**)&pXH, g_XH);
        cudaGetSymbolAddress((void**)&pXL, g_XL);
        cudaGetSymbolAddress((void**)&pWH, g_WH);
        cudaGetSymbolAddress((void**)&pWL, g_WL);
        cudaGetSymbolAddress((void**)&pHH, g_HH);
        cudaGetSymbolAddress((void**)&pHL, g_HL);
        cudaGetSymbolAddress((void**)&pYGH, g_YGH);
        cudaGetSymbolAddress((void**)&pYGL, g_YGL);
        cudaFuncSetAttribute(gemm_bf16, cudaFuncAttributeMaxDynamicSharedMemorySize, SMEM_REQ);
    }

    const long MH = (long)Mrows*128;
    auto GA = [&](const bf16* Ah, const bf16* Al, long wOff,
                  float* Cf, bf16* ChH, bf16* ChL,
                  const float* bias, const float* vaux, int epi, int outmode) {
        GArg a;
        a.Ah = Ah; a.Al = Al; a.Bh = pWH + wOff; a.Bl = pWL + wOff;
        a.Cf = Cf; a.ChH = ChH; a.ChL = ChL;
        a.bias = bias; a.vaux = vaux; a.epi = epi; a.outmode = outmode;
        return a;
    };

    // launch 0: prep
    prep_kernel<<<BTC/1024, 256>>>(x, maa_r, maa_w, maa_k, maa_v, maa_a, maa_g);

    // launch 1: all weight splits fused
    WPtrs wp;
    wp.w[0]=W_r; wp.w[1]=W_k; wp.w[2]=W_v; wp.w[3]=W_out;
    wp.w[4]=decay_w1; wp.w[5]=aaa_w1; wp.w[6]=gate_w1; wp.w[7]=mv_w1;
    wp.w[8]=decay_w2; wp.w[9]=aaa_w2; wp.w[10]=gate_w2; wp.w[11]=mv_w2;
    wsplit_all<<<20480, 256>>>(wp);

    // launch 2: ALL four LoRA stage-1 GEMMs fused (z=4; 512 CTAs)
    GArg aW  = GA(pXH+1l*BTC, pXL+1l*BTC, W_L(0), nullptr, pHH+0*MH, pHL+0*MH, nullptr, nullptr, 4, 1);
    GArg aA  = GA(pXH+4l*BTC, pXL+4l*BTC, W_L(1), nullptr, pHH+1*MH, pHL+1*MH, nullptr, nullptr, 0, 1);
    GArg aG  = GA(pXH+5l*BTC, pXL+5l*BTC, W_L(2), nullptr, pHH+2*MH, pHL+2*MH, nullptr, nullptr, 5, 1);
    GArg aMV = GA(pXH+3l*BTC, pXL+3l*BTC, W_L(3), nullptr, pHH+3*MH, pHL+3*MH, nullptr, nullptr, 0, 1);
    gemm_bf16<<<dim3(1,128,4),256,SMEM_REQ>>>(aW, aA, aG, aMV, 128, 1024);

    // launch 3: three stage-2 GEMMs fused (z=3; vmix b3 must wait for V)
    GArg b0 = GA(pHH+0*MH, pHL+0*MH, W_L(4), pWD, nullptr, nullptr, tdecay, nullptr, 1, 0);
    GArg b1 = GA(pHH+1*MH, pHL+1*MH, W_L(5), pA,  nullptr, nullptr, taaaaa, nullptr, 2, 0);
    GArg b2 = GA(pHH+2*MH, pHL+2*MH, W_L(6), pG,  nullptr, nullptr, nullptr, nullptr, 0, 0);
    gemm_bf16<<<dim3(8,128,3),256,SMEM_REQ>>>(b0, b1, b2, b0, 1024, 128);

    // launch 4: fused R/K/V projections  <-- ncu (-s 5 with harness offset 1) profiles THIS
    GArg aR = GA(pXH+0l*BTC, pXL+0l*BTC, W_R, pR, nullptr, nullptr, nullptr, nullptr, 0, 0);
    GArg aK = GA(pXH+2l*BTC, pXL+2l*BTC, W_K, pK, nullptr, nullptr, nullptr, nullptr, 0, 0);
    GArg aV = GA(pXH+3l*BTC, pXL+3l*BTC, W_V, pV, nullptr, nullptr, nullptr, nullptr, 0, 0);
    gemm_bf16<<<dim3(8,128,3),256,SMEM_REQ>>>(aR, aK, aV, aR, 1024, 1024);

    // launch 5: vmix stage-2 (needs V)
    GArg b3 = GA(pHH+3*MH, pHL+3*MH, W_L(7), pV, nullptr, nullptr, misc_v, v0, 3, 0);
    gemm_bf16<<<dim3(8,128,1),256,SMEM_REQ>>>(b3, b3, b3, b3, 1024, 128);

    // kk normalize + k update
    kk_kernel<<<(Bb*Tt*Hh)/8, 256>>>(pK, pA, misc_kkk, misc_a, pKK, pK);

    // sequential recurrence
    scan_kernel<<<Bb*Hh, 128>>>(pR, pWD, pK, pV, pKK, pA, pY);

    // groupnorm + bonus + gate -> bf16 planes
    post_kernel<<<(Bb*Tt*Hh)/8, 256>>>(pY, pR, pK, pV, pG, faaaa, ln_w, ln_b);

    // output projection
    GArg aO = GA(pYGH, pYGL, W_O, (float*)d_out, nullptr, nullptr, nullptr, nullptr, 0, 0);
    gemm_bf16<<<dim3(8,128,1),256,SMEM_REQ>>>(aO, aO, aO, aO, 1024, 1024);

    if (out_size >= 2*BTC)
        copy_kernel<<<(BTC/4 + 255)/256, 256>>>(v0, (float*)d_out + BTC, BTC/4);
}

// round 13
// speedup vs baseline: 1.1447x; 1.0013x over previous
#include <cuda_runtime.h>
#include <cuda_bf16.h>
#include <math.h>

#define Bb 8
#define Tt 2048
#define Cc 1024
#define Hh 16
#define Nn 64
#define Mrows 16384
#define BTC 16777216

typedef __nv_bfloat16 bf16;
typedef unsigned long long ull;

// ---------------- fp32 scratch ----------------
__device__ float g_R[BTC], g_K[BTC], g_V[BTC], g_A[BTC], g_G[BTC];
__device__ float g_WD[BTC], g_KK[BTC], g_Y[BTC];

// ---------------- bf16 hi/lo planes ----------------
__device__ __align__(256) bf16 g_XH[6l*BTC];
__device__ __align__(256) bf16 g_XL[6l*BTC];
__device__ __align__(256) bf16 g_WH[5242880];    // packed weights [K,N] padded
__device__ __align__(256) bf16 g_WL[5242880];
__device__ __align__(256) bf16 g_HH[4l*Mrows*128];
__device__ __align__(256) bf16 g_HL[4l*Mrows*128];
__device__ __align__(256) bf16 g_YGH[BTC];
__device__ __align__(256) bf16 g_YGL[BTC];

#define W_R  0
#define W_K  1048576
#define W_V  2097152
#define W_O  3145728
#define W_L(i) (4194304 + (i)*131072)

__device__ __forceinline__ float sigm(float x){ return 1.0f/(1.0f+expf(-x)); }
__device__ __forceinline__ void split2(float v, bf16& h, bf16& l){
    h = __float2bfloat16(v); l = __float2bfloat16(v - __bfloat162float(h));
}

__device__ __forceinline__ void cpa16(unsigned dst, const void* src) {
    asm volatile("cp.async.cg.shared.global [%0], [%1], 16;" :: "r"(dst), "l"(src));
}
__device__ __forceinline__ void cpcommit(){ asm volatile("cp.async.commit_group;"); }
__device__ __forceinline__ void cpwait1(){ asm volatile("cp.async.wait_group 1;"); }

__device__ __forceinline__ void ldmat4(unsigned& r0, unsigned& r1, unsigned& r2, unsigned& r3,
                                       unsigned addr) {
    asm volatile("ldmatrix.sync.aligned.m8n8.x4.shared.b16 {%0,%1,%2,%3}, [%4];"
                 : "=r"(r0), "=r"(r1), "=r"(r2), "=r"(r3) : "r"(addr));
}
__device__ __forceinline__ void ldmat4t(unsigned& r0, unsigned& r1, unsigned& r2, unsigned& r3,
                                        unsigned addr) {
    asm volatile("ldmatrix.sync.aligned.m8n8.x4.trans.shared.b16 {%0,%1,%2,%3}, [%4];"
                 : "=r"(r0), "=r"(r1), "=r"(r2), "=r"(r3) : "r"(addr));
}
__device__ __forceinline__ void mma16816(float* c, const unsigned* a, unsigned b0, unsigned b1) {
    asm volatile("mma.sync.aligned.m16n8k16.row.col.f32.bf16.bf16.f32 "
                 "{%0,%1,%2,%3}, {%4,%5,%6,%7}, {%8,%9}, {%0,%1,%2,%3};"
                 : "+f"(c[0]), "+f"(c[1]), "+f"(c[2]), "+f"(c[3])
                 : "r"(a[0]), "r"(a[1]), "r"(a[2]), "r"(a[3]), "r"(b0), "r"(b1));
}

// packed f32x2
__device__ __forceinline__ ull fma2(ull a, ull b, ull c){
    ull d; asm("fma.rn.f32x2 %0, %1, %2, %3;" : "=l"(d) : "l"(a), "l"(b), "l"(c)); return d;
}
__device__ __forceinline__ ull mul2(ull a, ull b){
    ull d; asm("mul.rn.f32x2 %0, %1, %2;" : "=l"(d) : "l"(a), "l"(b)); return d;
}
__device__ __forceinline__ ull pack2(float x){
    ull d; asm("mov.b64 %0, {%1, %1};" : "=l"(d) : "f"(x)); return d;
}
__device__ __forceinline__ float sum2(ull v){
    float lo, hi; asm("mov.b64 {%0, %1}, %2;" : "=f"(lo), "=f"(hi) : "l"(v)); return lo + hi;
}

// ============================================================================
// prep: mix x with 6 maa vectors, split to bf16 hi/lo planes.
// ============================================================================
__global__ void __launch_bounds__(256) prep_kernel(
    const float* __restrict__ x,
    const float* __restrict__ m0, const float* __restrict__ m1,
    const float* __restrict__ m2, const float* __restrict__ m3,
    const float* __restrict__ m4, const float* __restrict__ m5)
{
    long e = ((long)blockIdx.x*256 + threadIdx.x)*4;
    int r = (int)(e >> 10), c = (int)(e & 1023);
    float4 cur = *(const float4*)(x + e);
    float4 prv = make_float4(0.f,0.f,0.f,0.f);
    if ((r & (Tt-1)) != 0) prv = *(const float4*)(x + e - Cc);
    float d0 = prv.x-cur.x, d1 = prv.y-cur.y, d2 = prv.z-cur.z, d3 = prv.w-cur.w;
    const float* maas[6] = {m0,m1,m2,m3,m4,m5};
    #pragma unroll
    for (int v = 0; v < 6; v++) {
        float4 mv = *(const float4*)(maas[v] + c);
        float a0 = cur.x + d0*mv.x, a1 = cur.y + d1*mv.y;
        float a2 = cur.z + d2*mv.z, a3 = cur.w + d3*mv.w;
        bf16 h0,l0,h1,l1,h2,l2,h3,l3;
        split2(a0,h0,l0); split2(a1,h1,l1); split2(a2,h2,l2); split2(a3,h3,l3);
        long o = (long)v*BTC + e;
        *(__nv_bfloat162*)&g_XH[o]   = __nv_bfloat162(h0,h1);
        *(__nv_bfloat162*)&g_XH[o+2] = __nv_bfloat162(h2,h3);
        *(__nv_bfloat162*)&g_XL[o]   = __nv_bfloat162(l0,l1);
        *(__nv_bfloat162*)&g_XL[o+2] = __nv_bfloat162(l2,l3);
    }
}

// ============================================================================
// wsplit_all: split ALL weights in one launch.
// ============================================================================
struct WPtrs { const float* w[12]; };

__global__ void __launch_bounds__(256) wsplit_all(WPtrs p)
{
    long g = (long)blockIdx.x*256 + threadIdx.x;   // < 5242880
    float v;
    if (g < 4194304) {
        int which = (int)(g >> 20);
        int off = (int)(g & 1048575);
        v = p.w[which][off];
    } else {
        long h = g - 4194304;
        int i = (int)(h >> 17);
        int off = (int)(h & 131071);
        if (i < 4) {              // stage-1: [1024, Nreal] -> padded [1024,128]
            int r = off >> 7, c = off & 127;
            int Nreal = (i==2) ? 128 : ((i==3) ? 32 : 64);
            v = (c < Nreal) ? p.w[4+i][(long)r*Nreal + c] : 0.f;
        } else {                  // stage-2: [Kreal, 1024] -> padded [128,1024]
            int j = i - 4;
            int r = off >> 10, c = off & 1023;
            int Kreal = (j==2) ? 128 : ((j==3) ? 32 : 64);
            v = (r < Kreal) ? p.w[8+j][(long)r*1024 + c] : 0.f;
        }
    }
    bf16 hh, ll; split2(v, hh, ll);
    g_WH[g] = hh; g_WL[g] = ll;
}

// ============================================================================
// mma.sync GEMM: C[M,N] = A[M,K] @ B[K,N], bf16 hi/lo 3-pass, fp32 accum.
// CTA tile 128x128, BK=32, 3-stage cp.async, ONE barrier per k-iter.
// __launch_bounds__(256,2). blockIdx.z selects one of 4 GArg sets.
// Inner loop interleaves ldmatrix batches with MMA passes.
// ============================================================================
#define AST 40
#define BST 136
#define A_PL 10240           // bytes per A plane (128*40*2)
#define B_OFF 20480
#define B_PL 8704            // bytes per B plane (32*136*2)
#define STG 37888
#define SMEM_REQ (3*STG)     // 113664 B -> 2 CTAs/SM

struct GArg {
    const bf16 *Ah, *Al, *Bh, *Bl;
    float* Cf; bf16 *ChH, *ChL;
    const float *bias, *vaux;
    int epi, outmode;
};

__global__ void __launch_bounds__(256,2) gemm_bf16(GArg g0, GArg g1, GArg g2, GArg g3,
                                                   int N, int K)
{
    extern __shared__ __align__(16) char smem[];
    const unsigned smemU = (unsigned)__cvta_generic_to_shared(smem);

    const int bz = blockIdx.z;
    const GArg ga = (bz == 0) ? g0 : ((bz == 1) ? g1 : ((bz == 2) ? g2 : g3));
    const bf16* __restrict__ Ah = ga.Ah;  const bf16* __restrict__ Al = ga.Al;
    const bf16* __restrict__ Bh = ga.Bh;  const bf16* __restrict__ Bl = ga.Bl;

    const int tid  = threadIdx.x;
    const int bm   = blockIdx.y, bn = blockIdx.x;
    const int warp = tid >> 5, lane = tid & 31;
    const int wm   = warp & 1,  wn  = warp >> 1;

    float acc[4][4][4];
    #pragma unroll
    for (int i = 0; i < 4; i++)
        #pragma unroll
        for (int j = 0; j < 4; j++)
            #pragma unroll
            for (int e = 0; e < 4; e++) acc[i][j][e] = 0.f;

    const int aRow  = wm*64 + (lane & 7) + ((lane >> 3) & 1)*8;
    const int aCsel = (lane >> 4)*8;
    const unsigned aBaseOff = (unsigned)(aRow*AST + aCsel)*2;
    const int bKrow = ((lane >> 3) & 1)*8 + (lane & 7);
    const int bNcol = wn*32 + (lane >> 4)*8;
    const unsigned bBaseOff = (unsigned)(bKrow*BST + bNcol)*2;

    const int NIT = K >> 5;

    const int ar = tid >> 2, ac = (tid & 3)*8;
    const int br = tid >> 4, bc = (tid & 15)*8;
    auto issue = [&](int s, int k0) {
        unsigned sb = smemU + s*STG;
        #pragma unroll
        for (int u = 0; u < 2; u++) {
            int r = ar + u*64;
            unsigned so = (unsigned)(r*AST + ac)*2;
            cpa16(sb + so,        Ah + (long)(bm*128 + r)*K + k0 + ac);
            cpa16(sb + A_PL + so, Al + (long)(bm*128 + r)*K + k0 + ac);
            int r2 = br + u*16;
            unsigned so2 = (unsigned)(r2*BST + bc)*2;
            cpa16(sb + B_OFF + so2,        Bh + (long)(k0 + r2)*N + bn*128 + bc);
            cpa16(sb + B_OFF + B_PL + so2, Bl + (long)(k0 + r2)*N + bn*128 + bc);
        }
        cpcommit();
    };

    issue(0, 0);
    issue(1, 32);

    for (int s = 0; s < NIT; s++) {
        cpwait1();
        __syncthreads();
        if (s + 2 < NIT) issue((s + 2) % 3, (s + 2)*32); else cpcommit();

        unsigned sb = smemU + (s % 3)*STG;
        unsigned aH = sb + aBaseOff;
        unsigned aL = aH + A_PL;
        unsigned bH = sb + B_OFF + bBaseOff;
        unsigned bL = bH + B_PL;

        #pragma unroll
        for (int ks = 0; ks < 2; ks++) {
            unsigned ah[4][4], al[4][4], bh[2][4], bl[2][4];
            // batch 1: ah, bh, al in flight
            #pragma unroll
            for (int i = 0; i < 4; i++) {
                unsigned off = (unsigned)(i*16*AST + ks*16)*2;
                ldmat4(ah[i][0], ah[i][1], ah[i][2], ah[i][3], aH + off);
            }
            #pragma unroll
            for (int jj = 0; jj < 2; jj++) {
                unsigned off = (unsigned)(ks*16*BST + jj*16)*2;
                ldmat4t(bh[jj][0], bh[jj][1], bh[jj][2], bh[jj][3], bH + off);
            }
            #pragma unroll
            for (int i = 0; i < 4; i++) {
                unsigned off = (unsigned)(i*16*AST + ks*16)*2;
                ldmat4(al[i][0], al[i][1], al[i][2], al[i][3], aL + off);
            }
            // pass 1: ah*bh (covers al loads)
            #pragma unroll
            for (int i = 0; i < 4; i++)
                #pragma unroll
                for (int j = 0; j < 4; j++) {
                    int jj = j >> 1, sel = (j & 1)*2;
                    mma16816(acc[i][j], ah[i], bh[jj][sel], bh[jj][sel+1]);
                }
            // issue bl loads, covered by pass 3
            #pragma unroll
            for (int jj = 0; jj < 2; jj++) {
                unsigned off = (unsigned)(ks*16*BST + jj*16)*2;
                ldmat4t(bl[jj][0], bl[jj][1], bl[jj][2], bl[jj][3], bL + off);
            }
            // pass 3: al*bh
            #pragma unroll
            for (int i = 0; i < 4; i++)
                #pragma unroll
                for (int j = 0; j < 4; j++) {
                    int jj = j >> 1, sel = (j & 1)*2;
                    mma16816(acc[i][j], al[i], bh[jj][sel], bh[jj][sel+1]);
                }
            // pass 2: ah*bl
            #pragma unroll
            for (int i = 0; i < 4; i++)
                #pragma unroll
                for (int j = 0; j < 4; j++) {
                    int jj = j >> 1, sel = (j & 1)*2;
                    mma16816(acc[i][j], ah[i], bl[jj][sel], bl[jj][sel+1]);
                }
        }
    }

    // ---- epilogue ----
    const int g = lane >> 2, q = lane & 3;
    #pragma unroll
    for (int i = 0; i < 4; i++) {
        int r0 = bm*128 + wm*64 + i*16 + g;
        #pragma unroll
        for (int j = 0; j < 4; j++) {
            int col = bn*128 + wn*32 + j*8 + q*2;
            #pragma unroll
            for (int h = 0; h < 2; h++) {
                int row = r0 + h*8;
                long idx = (long)row*N + col;
                float v0 = acc[i][j][h*2], v1 = acc[i][j][h*2+1];
                if (ga.epi == 1) {
                    v0 = expf(-sigm(ga.bias[col]  +v0)*0.60653065971263342f);
                    v1 = expf(-sigm(ga.bias[col+1]+v1)*0.60653065971263342f);
                } else if (ga.epi == 2) {
                    v0 = sigm(ga.bias[col]+v0); v1 = sigm(ga.bias[col+1]+v1);
                } else if (ga.epi == 3) {
                    float s0 = sigm(ga.bias[col]+v0), s1 = sigm(ga.bias[col+1]+v1);
                    float c0 = ga.Cf[idx], c1 = ga.Cf[idx+1];
                    v0 = c0 + (ga.vaux[idx]  -c0)*s0;
                    v1 = c1 + (ga.vaux[idx+1]-c1)*s1;
                } else if (ga.epi == 4) {
                    v0 = tanhf(v0); v1 = tanhf(v1);
                } else if (ga.epi == 5) {
                    v0 = sigm(v0); v1 = sigm(v1);
                }
                if (ga.outmode == 0) {
                    *(float2*)&ga.Cf[idx] = make_float2(v0, v1);
                } else {
                    bf16 h0,l0,h1,l1;
                    split2(v0,h0,l0); split2(v1,h1,l1);
                    *(__nv_bfloat162*)&ga.ChH[idx] = __nv_bfloat162(h0,h1);
                    *(__nv_bfloat162*)&ga.ChL[idx] = __nv_bfloat162(l0,l1);
                }
            }
        }
    }
}

// ============================================================================
// kk normalize + k update.
// ============================================================================
__global__ void kk_kernel(const float* __restrict__ Kin, const float* __restrict__ Aa,
                          const float* __restrict__ mkk, const float* __restrict__ ma,
                          float* __restrict__ KKo, float* __restrict__ K2o)
{
    int gw   = (blockIdx.x*blockDim.x + threadIdx.x) >> 5;
    int lane = threadIdx.x & 31;
    long off = (long)gw*64 + lane*2;
    int  c   = ((gw & (Hh-1))*64) + lane*2;
    float2 kv = *(const float2*)(Kin + off);
    float2 mk = *(const float2*)(mkk + c);
    float kk0 = kv.x*mk.x, kk1 = kv.y*mk.y;
    float ss = kk0*kk0 + kk1*kk1;
    #pragma unroll
    for (int s = 16; s > 0; s >>= 1) ss += __shfl_xor_sync(0xffffffffu, ss, s);
    float inv = 1.0f / fmaxf(sqrtf(ss), 1e-12f);
    *(float2*)(KKo + off) = make_float2(kk0*inv, kk1*inv);
    float2 av  = *(const float2*)(Aa + off);
    float2 mav = *(const float2*)(ma + c);
    *(float2*)(K2o + off) = make_float2(kv.x*(1.f+(av.x-1.f)*mav.x),
                                        kv.y*(1.f+(av.y-1.f)*mav.y));
}

// ============================================================================
// RWKV7 scan: 128 threads per (b,h); thread owns half a state row; f32x2 FMA.
// ============================================================================
__global__ void __launch_bounds__(128) scan_kernel(
    const float* __restrict__ R,  const float* __restrict__ W,
    const float* __restrict__ K2, const float* __restrict__ V,
    const float* __restrict__ KK, const float* __restrict__ Aa,
    float* __restrict__ Y)
{
    const int bh = blockIdx.x;
    const int b  = bh >> 4, hh = bh & 15;
    const int tid  = threadIdx.x;
    const int i    = tid >> 1;
    const int half = tid & 1;
    const int cb   = half*32;
    const long rowbase = (long)b*Tt*Cc + hh*Nn;

    __shared__ __align__(16) float sm[2][6][Nn];

    ull S2[16];
    #pragma unroll
    for (int j = 0; j < 16; j++) S2[j] = 0ull;

    auto loadstage = [&](int q, int t) {
        long idx = rowbase + (long)t*Cc;
        if (tid < 64) {
            sm[q][0][tid] = R[idx+tid];
            sm[q][1][tid] = W[idx+tid];
            sm[q][2][tid] = K2[idx+tid];
        } else {
            int j = tid - 64;
            sm[q][3][j] = V[idx+j];
            float kk = KK[idx+j], a = Aa[idx+j];
            sm[q][4][j] = kk; sm[q][5][j] = kk*a;
        }
    };

    loadstage(0, 0);
    __syncthreads();

    int p = 0;
    for (int t = 0; t < Tt; t++) {
        if (t + 1 < Tt) loadstage(p^1, t+1);
        const ull* r2  = (const ull*)&sm[p][0][cb];
        const ull* w2  = (const ull*)&sm[p][1][cb];
        const ull* k2  = (const ull*)&sm[p][2][cb];
        const ull* kk2 = (const ull*)&sm[p][4][cb];
        const ull* b2  = (const ull*)&sm[p][5][cb];
        const float vi = sm[p][3][i];

        ull sa_a = 0ull, sa_b = 0ull;
        #pragma unroll
        for (int j = 0; j < 16; j += 2) {
            sa_a = fma2(S2[j],   kk2[j],   sa_a);
            sa_b = fma2(S2[j+1], kk2[j+1], sa_b);
        }
        float sa_p = sum2(sa_a) + sum2(sa_b);
        float sa = -(sa_p + __shfl_xor_sync(0xffffffffu, sa_p, 1));

        ull sa2 = pack2(sa), vi2 = pack2(vi);
        ull o_a = 0ull, o_b = 0ull;
        #pragma unroll
        for (int j = 0; j < 16; j += 2) {
            ull t0 = fma2(sa2, b2[j],   mul2(vi2, k2[j]));
            ull t1 = fma2(sa2, b2[j+1], mul2(vi2, k2[j+1]));
            S2[j]   = fma2(S2[j],   w2[j],   t0);
            S2[j+1] = fma2(S2[j+1], w2[j+1], t1);
            o_a = fma2(S2[j],   r2[j],   o_a);
            o_b = fma2(S2[j+1], r2[j+1], o_b);
        }
        float o_p = sum2(o_a) + sum2(o_b);
        float o = o_p + __shfl_xor_sync(0xffffffffu, o_p, 1);
        if (half == 0) Y[rowbase + (long)t*Cc + i] = o;
        __syncthreads();
        p ^= 1;
    }
}

// ============================================================================
// GroupNorm + rkv bonus + gate -> bf16 hi/lo planes.
// ============================================================================
__global__ void post_kernel(const float* __restrict__ Y,  const float* __restrict__ R,
                            const float* __restrict__ K2, const float* __restrict__ V,
                            const float* __restrict__ G,  const float* __restrict__ faaaa,
                            const float* __restrict__ lnw,const float* __restrict__ lnb)
{
    int gw   = (blockIdx.x*blockDim.x + threadIdx.x) >> 5;
    int lane = threadIdx.x & 31;
    long off = (long)gw*64 + lane*2;
    int  c   = ((gw & 15)*64) + lane*2;
    float2 y  = *(const float2*)(Y + off);
    float2 r  = *(const float2*)(R + off);
    float2 k  = *(const float2*)(K2 + off);
    float2 fa = *(const float2*)(faaaa + c);
    float s1 = y.x + y.y;
    float s2 = y.x*y.x + y.y*y.y;
    float rk = r.x*k.x*fa.x + r.y*k.y*fa.y;
    #pragma unroll
    for (int s = 16; s > 0; s >>= 1) {
        s1 += __shfl_xor_sync(0xffffffffu, s1, s);
        s2 += __shfl_xor_sync(0xffffffffu, s2, s);
        rk += __shfl_xor_sync(0xffffffffu, rk, s);
    }
    float mu  = s1 * (1.0f/64.0f);
    float var = s2 * (1.0f/64.0f) - mu*mu;
    float rs  = rsqrtf(var + 6.4e-4f);
    float2 w2 = *(const float2*)(lnw + c);
    float2 b2 = *(const float2*)(lnb + c);
    float2 v  = *(const float2*)(V + off);
    float2 g  = *(const float2*)(G + off);
    float o0 = ((y.x-mu)*rs*w2.x + b2.x + rk*v.x) * g.x;
    float o1 = ((y.y-mu)*rs*w2.y + b2.y + rk*v.y) * g.y;
    bf16 h0,l0,h1,l1;
    split2(o0,h0,l0); split2(o1,h1,l1);
    *(__nv_bfloat162*)&g_YGH[off] = __nv_bfloat162(h0,h1);
    *(__nv_bfloat162*)&g_YGL[off] = __nv_bfloat162(l0,l1);
}

__global__ void copy_kernel(const float* __restrict__ src, float* __restrict__ dst, int n4)
{
    int idx = blockIdx.x*blockDim.x + threadIdx.x;
    if (idx < n4) ((float4*)dst)[idx] = ((const float4*)src)[idx];
}

// ============================================================================
extern "C" void kernel_launch(void* const* d_in, const int* in_sizes, int n_in,
                              void* d_out, int out_size)
{
    const float* x        = (const float*)d_in[0];
    const float* v0       = (const float*)d_in[1];
    const float* maa_r    = (const float*)d_in[2];
    const float* maa_w    = (const float*)d_in[3];
    const float* maa_k    = (const float*)d_in[4];
    const float* maa_v    = (const float*)d_in[5];
    const float* maa_a    = (const float*)d_in[6];
    const float* maa_g    = (const float*)d_in[7];
    const float* tdecay   = (const float*)d_in[8];
    const float* faaaa    = (const float*)d_in[9];
    const float* taaaaa   = (const float*)d_in[10];
    const float* decay_w1 = (const float*)d_in[11];
    const float* decay_w2 = (const float*)d_in[12];
    const float* aaa_w1   = (const float*)d_in[13];
    const float* aaa_w2   = (const float*)d_in[14];
    const float* gate_w1  = (const float*)d_in[15];
    const float* gate_w2  = (const float*)d_in[16];
    const float* mv_w1    = (const float*)d_in[17];
    const float* mv_w2    = (const float*)d_in[18];
    const float* misc_v   = (const float*)d_in[19];
    const float* misc_kkk = (const float*)d_in[20];
    const float* misc_a   = (const float*)d_in[21];
    const float* W_r      = (const float*)d_in[22];
    const float* W_k      = (const float*)d_in[23];
    const float* W_v      = (const float*)d_in[24];
    const float* W_out    = (const float*)d_in[25];
    const float* ln_w     = (const float*)d_in[26];
    const float* ln_b     = (const float*)d_in[27];

    static float *pR=nullptr,*pK,*pV,*pA,*pG,*pWD,*pKK,*pY;
    static bf16 *pXH,*pXL,*pWH,*pWL,*pHH,*pHL,*pYGH,*pYGL;
    if (!pR) {
        cudaGetSymbolAddress((void**)&pR,  g_R);
        cudaGetSymbolAddress((void**)&pK,  g_K);
        cudaGetSymbolAddress((void**)&pV,  g_V);
        cudaGetSymbolAddress((void**)&pA,  g_A);
        cudaGetSymbolAddress((void**)&pG,  g_G);
        cudaGetSymbolAddress((void**)&pWD, g_WD);
        cudaGetSymbolAddress((void**)&pKK, g_KK);
        cudaGetSymbolAddress((void**)&pY,  g_Y);
        cudaGetSymbolAddress((void**)&pXH, g_XH);
        cudaGetSymbolAddress((void**)&pXL, g_XL);
        cudaGetSymbolAddress((void**)&pWH, g_WH);
        cudaGetSymbolAddress((void**)&pWL, g_WL);
        cudaGetSymbolAddress((void**)&pHH, g_HH);
        cudaGetSymbolAddress((void**)&pHL, g_HL);
        cudaGetSymbolAddress((void**)&pYGH, g_YGH);
        cudaGetSymbolAddress((void**)&pYGL, g_YGL);
        cudaFuncSetAttribute(gemm_bf16, cudaFuncAttributeMaxDynamicSharedMemorySize, SMEM_REQ);
    }

    const long MH = (long)Mrows*128;
    auto GA = [&](const bf16* Ah, const bf16* Al, long wOff,
                  float* Cf, bf16* ChH, bf16* ChL,
                  const float* bias, const float* vaux, int epi, int outmode) {
        GArg a;
        a.Ah = Ah; a.Al = Al; a.Bh = pWH + wOff; a.Bl = pWL + wOff;
        a.Cf = Cf; a.ChH = ChH; a.ChL = ChL;
        a.bias = bias; a.vaux = vaux; a.epi = epi; a.outmode = outmode;
        return a;
    };

    // launch 0: prep
    prep_kernel<<<BTC/1024, 256>>>(x, maa_r, maa_w, maa_k, maa_v, maa_a, maa_g);

    // launch 1: all weight splits fused
    WPtrs wp;
    wp.w[0]=W_r; wp.w[1]=W_k; wp.w[2]=W_v; wp.w[3]=W_out;
    wp.w[4]=decay_w1; wp.w[5]=aaa_w1; wp.w[6]=gate_w1; wp.w[7]=mv_w1;
    wp.w[8]=decay_w2; wp.w[9]=aaa_w2; wp.w[10]=gate_w2; wp.w[11]=mv_w2;
    wsplit_all<<<20480, 256>>>(wp);

    // launch 2: ALL four LoRA stage-1 GEMMs fused (z=4; 512 CTAs)
    GArg aW  = GA(pXH+1l*BTC, pXL+1l*BTC, W_L(0), nullptr, pHH+0*MH, pHL+0*MH, nullptr, nullptr, 4, 1);
    GArg aA  = GA(pXH+4l*BTC, pXL+4l*BTC, W_L(1), nullptr, pHH+1*MH, pHL+1*MH, nullptr, nullptr, 0, 1);
    GArg aG  = GA(pXH+5l*BTC, pXL+5l*BTC, W_L(2), nullptr, pHH+2*MH, pHL+2*MH, nullptr, nullptr, 5, 1);
    GArg aMV = GA(pXH+3l*BTC, pXL+3l*BTC, W_L(3), nullptr, pHH+3*MH, pHL+3*MH, nullptr, nullptr, 0, 1);
    gemm_bf16<<<dim3(1,128,4),256,SMEM_REQ>>>(aW, aA, aG, aMV, 128, 1024);

    // launch 3: three stage-2 GEMMs fused (z=3; vmix b3 must wait for V)
    GArg b0 = GA(pHH+0*MH, pHL+0*MH, W_L(4), pWD, nullptr, nullptr, tdecay, nullptr, 1, 0);
    GArg b1 = GA(pHH+1*MH, pHL+1*MH, W_L(5), pA,  nullptr, nullptr, taaaaa, nullptr, 2, 0);
    GArg b2 = GA(pHH+2*MH, pHL+2*MH, W_L(6), pG,  nullptr, nullptr, nullptr, nullptr, 0, 0);
    gemm_bf16<<<dim3(8,128,3),256,SMEM_REQ>>>(b0, b1, b2, b0, 1024, 128);

    // launch 4: fused R/K/V projections  <-- ncu (-s 5 with harness offset 1) profiles THIS
    GArg aR = GA(pXH+0l*BTC, pXL+0l*BTC, W_R, pR, nullptr, nullptr, nullptr, nullptr, 0, 0);
    GArg aK = GA(pXH+2l*BTC, pXL+2l*BTC, W_K, pK, nullptr, nullptr, nullptr, nullptr, 0, 0);
    GArg aV = GA(pXH+3l*BTC, pXL+3l*BTC, W_V, pV, nullptr, nullptr, nullptr, nullptr, 0, 0);
    gemm_bf16<<<dim3(8,128,3),256,SMEM_REQ>>>(aR, aK, aV, aR, 1024, 1024);

    // launch 5: vmix stage-2 (needs V)
    GArg b3 = GA(pHH+3*MH, pHL+3*MH, W_L(7), pV, nullptr, nullptr, misc_v, v0, 3, 0);
    gemm_bf16<<<dim3(8,128,1),256,SMEM_REQ>>>(b3, b3, b3, b3, 1024, 128);

    // kk normalize + k update
    kk_kernel<<<(Bb*Tt*Hh)/8, 256>>>(pK, pA, misc_kkk, misc_a, pKK, pK);

    // sequential recurrence
    scan_kernel<<<Bb*Hh, 128>>>(pR, pWD, pK, pV, pKK, pA, pY);

    // groupnorm + bonus + gate -> bf16 planes
    post_kernel<<<(Bb*Tt*Hh)/8, 256>>>(pY, pR, pK, pV, pG, faaaa, ln_w, ln_b);

    // output projection
    GArg aO = GA(pYGH, pYGL, W_O, (float*)d_out, nullptr, nullptr, nullptr, nullptr, 0, 0);
    gemm_bf16<<<dim3(8,128,1),256,SMEM_REQ>>>(aO, aO, aO, aO, 1024, 1024);

    if (out_size >= 2*BTC)
        copy_kernel<<<(BTC/4 + 255)/256, 256>>>(v0, (float*)d_out + BTC, BTC/4);
}